// round 2
// baseline (speedup 1.0000x reference)
#include <cuda_runtime.h>

#define N_NODES  50000
#define N_EDGES  800000
#define E_TOT    850000   // edges + self loops
#define IN_F     768
#define HID2     128
#define NHID     64
#define N_GRAPHS 128

// ---------------- scratch (device globals; no runtime allocation) ----------
__device__ float g_xw[(size_t)N_NODES * HID2];   // linear-transform output
__device__ float g_h [(size_t)N_NODES * HID2];   // layer output
__device__ float g_es[N_NODES];
__device__ float g_ed[N_NODES];
__device__ int   g_rowptr[N_NODES + 1];
__device__ int   g_counts[N_NODES];
__device__ int   g_fill[N_NODES];
__device__ int   g_srcidx[E_TOT];
__device__ int   g_is64;          // 1 if edge_index/batch are int64, 0 if int32

// ---------------- dtype-adaptive index loads --------------------------------
__device__ __forceinline__ int edge_src(const int* ei, int e) {
    return g_is64 ? (int)((const long long*)ei)[e] : ei[e];
}
__device__ __forceinline__ int edge_dst(const int* ei, int e) {
    return g_is64 ? (int)((const long long*)ei)[(size_t)N_EDGES + e]
                  : ei[(size_t)N_EDGES + e];
}
__device__ __forceinline__ int batch_at(const int* b, int i) {
    return g_is64 ? (int)((const long long*)b)[i] : b[i];
}

// Detect int64 vs int32: for little-endian int64 with values < 2^31, every
// odd 32-bit word is zero. For real int32 indices (uniform in [0,50000)),
// P(128 odd words all zero) ~ (1/50000)^128 ~ 0.
__global__ void k_detect_dtype(const int* __restrict__ ei) {
    int t = threadIdx.x;                 // 128 threads
    int nz = (ei[2 * t + 1] != 0) ? 1 : 0;
    int any = __syncthreads_or(nz);
    if (t == 0) g_is64 = any ? 0 : 1;
}

// ---------------- helpers ---------------------------------------------------
__device__ __forceinline__ float selu_f(float x) {
    const float sc = 1.0507009873554805f, al = 1.6732632423543772f;
    return x > 0.f ? sc * x : sc * al * expm1f(x);
}
__device__ __forceinline__ float lrelu02(float x) {
    return x > 0.f ? x : 0.2f * x;
}

// ---------------- CSR construction ------------------------------------------
__global__ void k_init_counts() {
    int i = blockIdx.x * blockDim.x + threadIdx.x;
    if (i < N_NODES) g_counts[i] = 1;   // self loop pre-counted
}

__global__ void k_histogram(const int* __restrict__ ei) {
    int e = blockIdx.x * blockDim.x + threadIdx.x;
    if (e < N_EDGES) {
        int dst = edge_dst(ei, e);
        atomicAdd(&g_counts[dst], 1);
    }
}

// single-block exclusive scan over 50000 counts -> rowptr[0..N]
__global__ void k_scan() {
    __shared__ int ssum[1024];
    const int CH = (N_NODES + 1023) / 1024;  // 49
    int t = threadIdx.x;
    int beg = t * CH;
    int end = min(beg + CH, N_NODES);
    int s = 0;
    for (int i = beg; i < end; i++) s += g_counts[i];
    ssum[t] = s;
    __syncthreads();
    for (int off = 1; off < 1024; off <<= 1) {
        int v = 0;
        if (t >= off) v = ssum[t - off];
        __syncthreads();
        ssum[t] += v;
        __syncthreads();
    }
    int excl = (t == 0) ? 0 : ssum[t - 1];
    for (int i = beg; i < end; i++) {
        g_rowptr[i] = excl;
        excl += g_counts[i];
    }
    if (t == 1023) g_rowptr[N_NODES] = ssum[1023];
}

__global__ void k_selfloop_fill() {
    int i = blockIdx.x * blockDim.x + threadIdx.x;
    if (i < N_NODES) {
        int p = g_rowptr[i];
        g_srcidx[p] = i;          // self loop first
        g_fill[i] = p + 1;
    }
}

__global__ void k_scatter(const int* __restrict__ ei) {
    int e = blockIdx.x * blockDim.x + threadIdx.x;
    if (e < N_EDGES) {
        int src = edge_src(ei, e);
        int dst = edge_dst(ei, e);
        int p = atomicAdd(&g_fill[dst], 1);
        g_srcidx[p] = src;
    }
}

// ---------------- tiled SGEMM: C[M,128] = A[M,K] @ B[K,128] -----------------
#define BM 64
#define BN 128
#define BKK 16
__global__ __launch_bounds__(256) void k_gemm(
    const float* __restrict__ A, const float* __restrict__ B,
    float* __restrict__ C, int M, int K)
{
    __shared__ float As[BKK][BM];   // transposed A tile
    __shared__ float Bs[BKK][BN];
    int tid = threadIdx.x;
    int block_row = blockIdx.x * BM;
    int tx = tid & 31;   // N tiles of 4
    int ty = tid >> 5;   // M tiles of 8
    float acc[8][4];
#pragma unroll
    for (int i = 0; i < 8; i++)
#pragma unroll
        for (int j = 0; j < 4; j++) acc[i][j] = 0.f;

    int arow = tid >> 2, acol = (tid & 3) * 4;
    for (int k0 = 0; k0 < K; k0 += BKK) {
        float4 av = make_float4(0.f, 0.f, 0.f, 0.f);
        int gr = block_row + arow;
        if (gr < M) av = *(const float4*)(A + (size_t)gr * K + k0 + acol);
        As[acol + 0][arow] = av.x;
        As[acol + 1][arow] = av.y;
        As[acol + 2][arow] = av.z;
        As[acol + 3][arow] = av.w;
#pragma unroll
        for (int i = 0; i < 2; i++) {
            int idx = tid + i * 256;
            int br = idx >> 5, bc = (idx & 31) * 4;
            float4 bv = *(const float4*)(B + (size_t)(k0 + br) * BN + bc);
            *(float4*)&Bs[br][bc] = bv;
        }
        __syncthreads();
#pragma unroll
        for (int k = 0; k < BKK; k++) {
            float a[8], b[4];
#pragma unroll
            for (int i = 0; i < 8; i++) a[i] = As[k][ty * 8 + i];
#pragma unroll
            for (int j = 0; j < 4; j++) b[j] = Bs[k][tx * 4 + j];
#pragma unroll
            for (int i = 0; i < 8; i++)
#pragma unroll
                for (int j = 0; j < 4; j++) acc[i][j] += a[i] * b[j];
        }
        __syncthreads();
    }
#pragma unroll
    for (int i = 0; i < 8; i++) {
        int r = block_row + ty * 8 + i;
        if (r < M) {
            float4 v = make_float4(acc[i][0], acc[i][1], acc[i][2], acc[i][3]);
            *(float4*)(C + (size_t)r * BN + tx * 4) = v;
        }
    }
}

// ---------------- attention scores: es/ed = xw @ a_src / a_dst ---------------
__global__ void k_attn_scores(const float* __restrict__ xw,
                              const float* __restrict__ a_s,
                              const float* __restrict__ a_d)
{
    int warp = (blockIdx.x * blockDim.x + threadIdx.x) >> 5;
    int lane = threadIdx.x & 31;
    if (warp >= N_NODES) return;
    float4 v  = ((const float4*)(xw + (size_t)warp * HID2))[lane];
    float4 s4 = ((const float4*)a_s)[lane];
    float4 d4 = ((const float4*)a_d)[lane];
    float es = v.x * s4.x + v.y * s4.y + v.z * s4.z + v.w * s4.w;
    float ed = v.x * d4.x + v.y * d4.y + v.z * d4.z + v.w * d4.w;
#pragma unroll
    for (int o = 16; o; o >>= 1) {
        es += __shfl_xor_sync(0xffffffffu, es, o);
        ed += __shfl_xor_sync(0xffffffffu, ed, o);
    }
    if (lane == 0) {
        g_es[warp] = es;
        g_ed[warp] = ed;
    }
}

// ---------------- GAT aggregation (warp per dst node) ------------------------
__global__ void k_gat_agg(const float* __restrict__ xw,
                          const float* __restrict__ bias,
                          float* __restrict__ out)
{
    int node = (blockIdx.x * blockDim.x + threadIdx.x) >> 5;
    int lane = threadIdx.x & 31;
    if (node >= N_NODES) return;
    int beg = g_rowptr[node], end = g_rowptr[node + 1];
    float edv = g_ed[node];

    // pass 1: max
    float m = -1e30f;
    for (int i = beg + lane; i < end; i += 32) {
        float e = lrelu02(g_es[g_srcidx[i]] + edv);
        m = fmaxf(m, e);
    }
#pragma unroll
    for (int o = 16; o; o >>= 1) m = fmaxf(m, __shfl_xor_sync(0xffffffffu, m, o));

    // pass 2: sum of exp
    float ssum = 0.f;
    for (int i = beg + lane; i < end; i += 32) {
        float e = lrelu02(g_es[g_srcidx[i]] + edv);
        ssum += __expf(e - m);
    }
#pragma unroll
    for (int o = 16; o; o >>= 1) ssum += __shfl_xor_sync(0xffffffffu, ssum, o);
    float inv = 1.f / ssum;

    // pass 3: weighted aggregate; each lane holds 4 channels
    float4 acc = make_float4(0.f, 0.f, 0.f, 0.f);
    for (int base = beg; base < end; base += 32) {
        int i = base + lane;
        float alpha = 0.f;
        int sidx = 0;
        if (i < end) {
            sidx = g_srcidx[i];
            float e = lrelu02(g_es[sidx] + edv);
            alpha = __expf(e - m) * inv;
        }
        int cnt = min(32, end - base);
        for (int j = 0; j < cnt; j++) {
            float a = __shfl_sync(0xffffffffu, alpha, j);
            int   s = __shfl_sync(0xffffffffu, sidx, j);
            float4 v = ((const float4*)(xw + (size_t)s * HID2))[lane];
            acc.x += a * v.x;
            acc.y += a * v.y;
            acc.z += a * v.z;
            acc.w += a * v.w;
        }
    }
    float4 b4 = ((const float4*)bias)[lane];
    float4 r;
    r.x = selu_f(acc.x + b4.x);
    r.y = selu_f(acc.y + b4.y);
    r.z = selu_f(acc.z + b4.z);
    r.w = selu_f(acc.w + b4.w);
    ((float4*)(out + (size_t)node * HID2))[lane] = r;
}

// ---------------- pool + MLP + log_softmax (block per graph) -----------------
__device__ __forceinline__ int lb_batch(const int* b, int n, int v) {
    int lo = 0, hi = n;
    while (lo < hi) {
        int mid = (lo + hi) >> 1;
        if (batch_at(b, mid) < v) lo = mid + 1; else hi = mid;
    }
    return lo;
}

__global__ void k_pool_mlp(const float* __restrict__ h,
                           const int* __restrict__ batch,
                           const float* __restrict__ fc1w,
                           const float* __restrict__ fc1b,
                           const float* __restrict__ fc2w,
                           const float* __restrict__ fc2b,
                           float* __restrict__ out)
{
    int g = blockIdx.x;        // 128 graphs
    int t = threadIdx.x;       // 128 threads
    __shared__ float pooled[HID2];
    __shared__ float hid[NHID];
    __shared__ float logits[2];

    int lo = lb_batch(batch, N_NODES, g);
    int hi = lb_batch(batch, N_NODES, g + 1);
    float s = 0.f;
    for (int i = lo; i < hi; i++) s += h[(size_t)i * HID2 + t];
    float cnt = (float)max(hi - lo, 1);
    pooled[t] = selu_f(s / cnt);
    __syncthreads();

    if (t < NHID) {
        float a = fc1b[t];
#pragma unroll 8
        for (int c = 0; c < HID2; c++) a += pooled[c] * fc1w[c * NHID + t];
        hid[t] = selu_f(a);
    }
    __syncthreads();

    if (t < 2) {
        float a = fc2b[t];
#pragma unroll 8
        for (int j = 0; j < NHID; j++) a += hid[j] * fc2w[j * 2 + t];
        logits[t] = a;
    }
    __syncthreads();

    if (t == 0) {
        float l0 = logits[0], l1 = logits[1];
        float mx = fmaxf(l0, l1);
        float lse = mx + logf(expf(l0 - mx) + expf(l1 - mx));
        out[g * 2 + 0] = l0 - lse;
        out[g * 2 + 1] = l1 - lse;
    }
}

// ---------------- launcher ---------------------------------------------------
extern "C" void kernel_launch(void* const* d_in, const int* in_sizes, int n_in,
                              void* d_out, int out_size)
{
    const float* x     = (const float*)d_in[0];
    const int*   ei    = (const int*)d_in[1];    // int32 or int64 (auto-detected)
    const int*   batch = (const int*)d_in[2];
    const float* W1    = (const float*)d_in[3];
    const float* as1   = (const float*)d_in[4];
    const float* ad1   = (const float*)d_in[5];
    const float* b1    = (const float*)d_in[6];
    const float* W2    = (const float*)d_in[7];
    const float* as2   = (const float*)d_in[8];
    const float* ad2   = (const float*)d_in[9];
    const float* b2    = (const float*)d_in[10];
    const float* fc1w  = (const float*)d_in[11];
    const float* fc1b  = (const float*)d_in[12];
    const float* fc2w  = (const float*)d_in[13];
    const float* fc2b  = (const float*)d_in[14];
    float* out = (float*)d_out;

    float* xw; cudaGetSymbolAddress((void**)&xw, g_xw);
    float* h;  cudaGetSymbolAddress((void**)&h,  g_h);

    // --- dtype detection + CSR build (dst-sorted) ---
    k_detect_dtype<<<1, 128>>>(ei);
    k_init_counts<<<(N_NODES + 255) / 256, 256>>>();
    k_histogram<<<(N_EDGES + 255) / 256, 256>>>(ei);
    k_scan<<<1, 1024>>>();
    k_selfloop_fill<<<(N_NODES + 255) / 256, 256>>>();
    k_scatter<<<(N_EDGES + 255) / 256, 256>>>(ei);

    const int GEMM_GRID = (N_NODES + BM - 1) / BM;
    const int WARP_GRID = (N_NODES * 32 + 255) / 256;

    // --- layer 1 ---
    k_gemm<<<GEMM_GRID, 256>>>(x, W1, xw, N_NODES, IN_F);
    k_attn_scores<<<WARP_GRID, 256>>>(xw, as1, ad1);
    k_gat_agg<<<WARP_GRID, 256>>>(xw, b1, h);

    // --- layer 2 (reuse xw buffer) ---
    k_gemm<<<GEMM_GRID, 256>>>(h, W2, xw, N_NODES, HID2);
    k_attn_scores<<<WARP_GRID, 256>>>(xw, as2, ad2);
    k_gat_agg<<<WARP_GRID, 256>>>(xw, b2, h);   // overwrite h in place (reads only xw/es/ed)

    // --- pool + MLP + log_softmax ---
    k_pool_mlp<<<N_GRAPHS, HID2>>>(h, batch, fc1w, fc1b, fc2w, fc2b, out);
}

// round 4
// speedup vs baseline: 1.3599x; 1.3599x over previous
#include <cuda_runtime.h>
#include <cuda_bf16.h>
#include <cstdint>

#define N_NODES  50000
#define N_EDGES  800000
#define E_TOT    850000
#define IN_F     768
#define HID2     128
#define NHID     64
#define N_GRAPHS 128
#define SCAN_NB  ((N_NODES + 255) / 256)   // 196

// ---------------- scratch (device globals; no runtime allocation) ----------
__device__ float g_xw[(size_t)N_NODES * HID2];
__device__ float g_h [(size_t)N_NODES * HID2];
__device__ __nv_bfloat16 g_h1h[(size_t)N_NODES * HID2];
__device__ __nv_bfloat16 g_h1l[(size_t)N_NODES * HID2];
__device__ __nv_bfloat16 g_w1h[(size_t)HID2 * IN_F];   // W1^T hi  [128][768]
__device__ __nv_bfloat16 g_w1l[(size_t)HID2 * IN_F];
__device__ __nv_bfloat16 g_w2h[(size_t)HID2 * HID2];   // W2^T hi  [128][128]
__device__ __nv_bfloat16 g_w2l[(size_t)HID2 * HID2];
__device__ float g_es[N_NODES];
__device__ float g_ed[N_NODES];
__device__ int   g_rowptr[N_NODES + 1];
__device__ int   g_counts[N_NODES];
__device__ int   g_fill[N_NODES];
__device__ int   g_srcidx[E_TOT];
__device__ int   g_blksum[256];
__device__ int   g_is64;

// ---------------- dtype-adaptive index loads --------------------------------
__device__ __forceinline__ int edge_src(const int* ei, int e) {
    return g_is64 ? (int)((const long long*)ei)[e] : ei[e];
}
__device__ __forceinline__ int edge_dst(const int* ei, int e) {
    return g_is64 ? (int)((const long long*)ei)[(size_t)N_EDGES + e]
                  : ei[(size_t)N_EDGES + e];
}
__device__ __forceinline__ int batch_at(const int* b, int i) {
    return g_is64 ? (int)((const long long*)b)[i] : b[i];
}

__global__ void k_detect_dtype(const int* __restrict__ ei) {
    int t = threadIdx.x;
    int nz = (ei[2 * t + 1] != 0) ? 1 : 0;
    int any = __syncthreads_or(nz);
    if (t == 0) g_is64 = any ? 0 : 1;
}

// ---------------- math helpers ----------------------------------------------
__device__ __forceinline__ float selu_f(float x) {
    const float sc = 1.0507009873554805f, al = 1.6732632423543772f;
    return x > 0.f ? sc * x : sc * al * expm1f(x);
}
__device__ __forceinline__ float lrelu02(float x) { return x > 0.f ? x : 0.2f * x; }

__device__ __forceinline__ uint32_t pack_bf2(float a, float b) {
    __nv_bfloat162 p(__float2bfloat16(a), __float2bfloat16(b));
    return *(uint32_t*)&p;
}

// ---------------- CSR construction ------------------------------------------
__global__ void k_init_counts() {
    int i = blockIdx.x * blockDim.x + threadIdx.x;
    if (i < N_NODES) g_counts[i] = 1;
}
__global__ void k_histogram(const int* __restrict__ ei) {
    int e = blockIdx.x * blockDim.x + threadIdx.x;
    if (e < N_EDGES) atomicAdd(&g_counts[edge_dst(ei, e)], 1);
}
__global__ void k_scan1() {
    __shared__ int sh[256];
    int b = blockIdx.x, t = threadIdx.x;
    int idx = b * 256 + t;
    sh[t] = (idx < N_NODES) ? g_counts[idx] : 0;
    __syncthreads();
    for (int off = 128; off; off >>= 1) {
        if (t < off) sh[t] += sh[t + off];
        __syncthreads();
    }
    if (t == 0) g_blksum[b] = sh[0];
}
__global__ void k_scan2() {
    __shared__ int sh[256];
    int t = threadIdx.x;
    int v = (t < SCAN_NB) ? g_blksum[t] : 0;
    sh[t] = v;
    __syncthreads();
    for (int off = 1; off < 256; off <<= 1) {
        int add = (t >= off) ? sh[t - off] : 0;
        __syncthreads();
        sh[t] += add;
        __syncthreads();
    }
    if (t < SCAN_NB) g_blksum[t] = sh[t] - v;     // exclusive
    if (t == 255) g_rowptr[N_NODES] = sh[255];
}
__global__ void k_scan3() {
    __shared__ int sh[256];
    int b = blockIdx.x, t = threadIdx.x;
    int idx = b * 256 + t;
    int v = (idx < N_NODES) ? g_counts[idx] : 0;
    sh[t] = v;
    __syncthreads();
    for (int off = 1; off < 256; off <<= 1) {
        int add = (t >= off) ? sh[t - off] : 0;
        __syncthreads();
        sh[t] += add;
        __syncthreads();
    }
    if (idx < N_NODES) g_rowptr[idx] = g_blksum[b] + sh[t] - v;
}
__global__ void k_selfloop_fill() {
    int i = blockIdx.x * blockDim.x + threadIdx.x;
    if (i < N_NODES) {
        int p = g_rowptr[i];
        g_srcidx[p] = i;
        g_fill[i] = p + 1;
    }
}
__global__ void k_scatter(const int* __restrict__ ei) {
    int e = blockIdx.x * blockDim.x + threadIdx.x;
    if (e < N_EDGES) {
        int src = edge_src(ei, e);
        int dst = edge_dst(ei, e);
        g_srcidx[atomicAdd(&g_fill[dst], 1)] = src;
    }
}

// ---------------- weight transpose + bf16 hi/lo split -------------------------
__global__ void k_conv_w(const float* __restrict__ W, int K,
                         __nv_bfloat16* __restrict__ Th, __nv_bfloat16* __restrict__ Tl) {
    int idx = blockIdx.x * blockDim.x + threadIdx.x;
    if (idx >= K * HID2) return;
    int n = idx & (HID2 - 1), k = idx >> 7;
    float v = W[(size_t)k * HID2 + n];
    __nv_bfloat16 h = __float2bfloat16(v);
    Th[(size_t)n * K + k] = h;
    Tl[(size_t)n * K + k] = __float2bfloat16(v - __bfloat162float(h));
}

// ---------------- mma.sync bf16-split GEMM + fused attention scores ----------
// C[128,128] CTA tile, 8 warps (2 m-halves x 4 n-quarters), warp tile 64x32.
// 3-MMA hi/lo split per k16 for fp32-level accuracy. Epilogue writes xw and
// per-row es/ed = xw . a_src / a_dst (fused; no separate pass over xw).
__device__ __forceinline__ void mma16816(float* c, const uint32_t* a, const uint32_t* b) {
    asm volatile(
        "mma.sync.aligned.m16n8k16.row.col.f32.bf16.bf16.f32 "
        "{%0,%1,%2,%3}, {%4,%5,%6,%7}, {%8,%9}, {%0,%1,%2,%3};"
        : "+f"(c[0]), "+f"(c[1]), "+f"(c[2]), "+f"(c[3])
        : "r"(a[0]), "r"(a[1]), "r"(a[2]), "r"(a[3]), "r"(b[0]), "r"(b[1]));
}

#define APAD 40   // bf16 stride: conflict-free quad-pattern LDS

template <int AMODE>   // 0: A fp32 (convert on load), 1: A bf16 hi/lo pair
__global__ __launch_bounds__(256) void k_gemm_mma(
    const float* __restrict__ Af,
    const __nv_bfloat16* __restrict__ Abh, const __nv_bfloat16* __restrict__ Abl,
    const __nv_bfloat16* __restrict__ Bh,  const __nv_bfloat16* __restrict__ Bl,
    int M, int K,
    const float* __restrict__ a_s, const float* __restrict__ a_d,
    float* __restrict__ xw)
{
    __shared__ __nv_bfloat16 sAh[128][APAD], sAl[128][APAD];
    __shared__ __nv_bfloat16 sBh[128][APAD], sBl[128][APAD];
    __shared__ float s_es[128], s_ed[128];

    int tid = threadIdx.x, lane = tid & 31, w = tid >> 5;
    int wm = w & 1, wn = w >> 1;               // 2 x 4 warp grid
    int block_row = blockIdx.x * 128;
    int q = lane >> 2, qr = lane & 3;          // quad id / quad rank

    float acc[4][4][4];
#pragma unroll
    for (int i = 0; i < 4; i++)
#pragma unroll
        for (int j = 0; j < 4; j++)
#pragma unroll
            for (int v = 0; v < 4; v++) acc[i][j][v] = 0.f;

    const int nchunks = K >> 5;                // K / 32
    for (int c = 0; c < nchunks; c++) {
        int k0 = c << 5;
        if (c) __syncthreads();                // protect prior-iter frag reads
        // ---- global -> smem: A (128 x 32) and B (128 x 32), hi/lo ----
#pragma unroll
        for (int it = 0; it < 4; it++) {
            int idx = tid + it * 256;
            int row = idx >> 3, col = (idx & 7) * 4;
            int grow = block_row + row;
            if (grow >= M) grow = M - 1;
            if (AMODE == 0) {
                float4 v = *(const float4*)(Af + (size_t)grow * K + k0 + col);
                uint2 uh, ul;
                uh.x = pack_bf2(v.x, v.y);
                uh.y = pack_bf2(v.z, v.w);
                float lx = v.x - __bfloat162float(__float2bfloat16(v.x));
                float ly = v.y - __bfloat162float(__float2bfloat16(v.y));
                float lz = v.z - __bfloat162float(__float2bfloat16(v.z));
                float lw = v.w - __bfloat162float(__float2bfloat16(v.w));
                ul.x = pack_bf2(lx, ly);
                ul.y = pack_bf2(lz, lw);
                *(uint2*)&sAh[row][col] = uh;
                *(uint2*)&sAl[row][col] = ul;
            } else {
                *(uint2*)&sAh[row][col] = *(const uint2*)(Abh + (size_t)grow * K + k0 + col);
                *(uint2*)&sAl[row][col] = *(const uint2*)(Abl + (size_t)grow * K + k0 + col);
            }
            *(uint2*)&sBh[row][col] = *(const uint2*)(Bh + (size_t)row * K + k0 + col);
            *(uint2*)&sBl[row][col] = *(const uint2*)(Bl + (size_t)row * K + k0 + col);
        }
        __syncthreads();
        // ---- two k16 steps ----
#pragma unroll
        for (int ks = 0; ks < 32; ks += 16) {
            int kk = ks + qr * 2;
            uint32_t ah[4][4], al[4][4];
#pragma unroll
            for (int i = 0; i < 4; i++) {
                int r = wm * 64 + i * 16 + q;
                ah[i][0] = *(const uint32_t*)&sAh[r][kk];
                ah[i][1] = *(const uint32_t*)&sAh[r + 8][kk];
                ah[i][2] = *(const uint32_t*)&sAh[r][kk + 8];
                ah[i][3] = *(const uint32_t*)&sAh[r + 8][kk + 8];
                al[i][0] = *(const uint32_t*)&sAl[r][kk];
                al[i][1] = *(const uint32_t*)&sAl[r + 8][kk];
                al[i][2] = *(const uint32_t*)&sAl[r][kk + 8];
                al[i][3] = *(const uint32_t*)&sAl[r + 8][kk + 8];
            }
#pragma unroll
            for (int j = 0; j < 4; j++) {
                int n = wn * 32 + j * 8 + q;
                uint32_t bh[2], bl[2];
                bh[0] = *(const uint32_t*)&sBh[n][kk];
                bh[1] = *(const uint32_t*)&sBh[n][kk + 8];
                bl[0] = *(const uint32_t*)&sBl[n][kk];
                bl[1] = *(const uint32_t*)&sBl[n][kk + 8];
#pragma unroll
                for (int i = 0; i < 4; i++) {
                    mma16816(acc[i][j], ah[i], bh);
                    mma16816(acc[i][j], ah[i], bl);
                    mma16816(acc[i][j], al[i], bh);
                }
            }
        }
    }

    // ---- epilogue: store xw + fused es/ed ----
    __syncthreads();
    if (tid < 128) { s_es[tid] = 0.f; s_ed[tid] = 0.f; }
    __syncthreads();

    float2 asv[4], adv[4];
#pragma unroll
    for (int j = 0; j < 4; j++) {
        int col = wn * 32 + j * 8 + qr * 2;
        asv[j] = *(const float2*)(a_s + col);
        adv[j] = *(const float2*)(a_d + col);
    }

#pragma unroll
    for (int i = 0; i < 4; i++) {
        int lrow = wm * 64 + i * 16 + q;       // local rows lrow, lrow+8
        int grow0 = block_row + lrow;
        int grow1 = grow0 + 8;
        float e0s = 0.f, e0d = 0.f, e1s = 0.f, e1d = 0.f;
#pragma unroll
        for (int j = 0; j < 4; j++) {
            int col = wn * 32 + j * 8 + qr * 2;
            float d0 = acc[i][j][0], d1 = acc[i][j][1];
            float d2 = acc[i][j][2], d3 = acc[i][j][3];
            if (grow0 < M) *(float2*)(xw + (size_t)grow0 * HID2 + col) = make_float2(d0, d1);
            if (grow1 < M) *(float2*)(xw + (size_t)grow1 * HID2 + col) = make_float2(d2, d3);
            e0s += d0 * asv[j].x + d1 * asv[j].y;
            e0d += d0 * adv[j].x + d1 * adv[j].y;
            e1s += d2 * asv[j].x + d3 * asv[j].y;
            e1d += d2 * adv[j].x + d3 * adv[j].y;
        }
#pragma unroll
        for (int off = 1; off < 4; off <<= 1) {
            e0s += __shfl_xor_sync(0xffffffffu, e0s, off);
            e0d += __shfl_xor_sync(0xffffffffu, e0d, off);
            e1s += __shfl_xor_sync(0xffffffffu, e1s, off);
            e1d += __shfl_xor_sync(0xffffffffu, e1d, off);
        }
        if (qr == 0) {
            atomicAdd(&s_es[lrow], e0s);
            atomicAdd(&s_ed[lrow], e0d);
            atomicAdd(&s_es[lrow + 8], e1s);
            atomicAdd(&s_ed[lrow + 8], e1d);
        }
    }
    __syncthreads();
    if (tid < 128) {
        int grow = block_row + tid;
        if (grow < M) {
            g_es[grow] = s_es[tid];
            g_ed[grow] = s_ed[tid];
        }
    }
}

// ---------------- GAT aggregation (warp per dst node) ------------------------
// OUT==0: fp32 out; OUT==1: bf16 hi/lo pair out (feeds next tensor GEMM)
template <int OUT>
__global__ void k_gat_agg(const float* __restrict__ xw,
                          const float* __restrict__ bias,
                          float* __restrict__ out_f32,
                          __nv_bfloat16* __restrict__ oh,
                          __nv_bfloat16* __restrict__ ol)
{
    int node = (blockIdx.x * blockDim.x + threadIdx.x) >> 5;
    int lane = threadIdx.x & 31;
    if (node >= N_NODES) return;
    int beg = g_rowptr[node], end = g_rowptr[node + 1];
    float edv = g_ed[node];

    float m = -1e30f;
    for (int i = beg + lane; i < end; i += 32)
        m = fmaxf(m, lrelu02(g_es[g_srcidx[i]] + edv));
#pragma unroll
    for (int o = 16; o; o >>= 1) m = fmaxf(m, __shfl_xor_sync(0xffffffffu, m, o));

    float ssum = 0.f;
    for (int i = beg + lane; i < end; i += 32)
        ssum += __expf(lrelu02(g_es[g_srcidx[i]] + edv) - m);
#pragma unroll
    for (int o = 16; o; o >>= 1) ssum += __shfl_xor_sync(0xffffffffu, ssum, o);
    float inv = 1.f / ssum;

    float4 acc = make_float4(0.f, 0.f, 0.f, 0.f);
    for (int base = beg; base < end; base += 32) {
        int i = base + lane;
        float alpha = 0.f;
        int sidx = 0;
        if (i < end) {
            sidx = g_srcidx[i];
            alpha = __expf(lrelu02(g_es[sidx] + edv) - m) * inv;
        }
        int cnt = min(32, end - base);
        for (int j = 0; j < cnt; j++) {
            float a = __shfl_sync(0xffffffffu, alpha, j);
            int   s = __shfl_sync(0xffffffffu, sidx, j);
            float4 v = ((const float4*)(xw + (size_t)s * HID2))[lane];
            acc.x += a * v.x; acc.y += a * v.y; acc.z += a * v.z; acc.w += a * v.w;
        }
    }
    float4 b4 = ((const float4*)bias)[lane];
    float r0 = selu_f(acc.x + b4.x), r1 = selu_f(acc.y + b4.y);
    float r2 = selu_f(acc.z + b4.z), r3 = selu_f(acc.w + b4.w);
    if (OUT == 0) {
        ((float4*)(out_f32 + (size_t)node * HID2))[lane] = make_float4(r0, r1, r2, r3);
    } else {
        size_t off = (size_t)node * HID2 + lane * 4;
        uint2 uh, ul;
        uh.x = pack_bf2(r0, r1);
        uh.y = pack_bf2(r2, r3);
        ul.x = pack_bf2(r0 - __bfloat162float(__float2bfloat16(r0)),
                        r1 - __bfloat162float(__float2bfloat16(r1)));
        ul.y = pack_bf2(r2 - __bfloat162float(__float2bfloat16(r2)),
                        r3 - __bfloat162float(__float2bfloat16(r3)));
        *(uint2*)(oh + off) = uh;
        *(uint2*)(ol + off) = ul;
    }
}

// ---------------- pool + MLP + log_softmax -----------------------------------
__device__ __forceinline__ int lb_batch(const int* b, int n, int v) {
    int lo = 0, hi = n;
    while (lo < hi) {
        int mid = (lo + hi) >> 1;
        if (batch_at(b, mid) < v) lo = mid + 1; else hi = mid;
    }
    return lo;
}

__global__ void k_pool_mlp(const float* __restrict__ h,
                           const int* __restrict__ batch,
                           const float* __restrict__ fc1w, const float* __restrict__ fc1b,
                           const float* __restrict__ fc2w, const float* __restrict__ fc2b,
                           float* __restrict__ out)
{
    int g = blockIdx.x, t = threadIdx.x;
    __shared__ float pooled[HID2];
    __shared__ float hid[NHID];
    __shared__ float logits[2];

    int lo = lb_batch(batch, N_NODES, g);
    int hi = lb_batch(batch, N_NODES, g + 1);
    float s = 0.f;
    for (int i = lo; i < hi; i++) s += h[(size_t)i * HID2 + t];
    pooled[t] = selu_f(s / (float)max(hi - lo, 1));
    __syncthreads();

    if (t < NHID) {
        float a = fc1b[t];
#pragma unroll 8
        for (int c = 0; c < HID2; c++) a += pooled[c] * fc1w[c * NHID + t];
        hid[t] = selu_f(a);
    }
    __syncthreads();
    if (t < 2) {
        float a = fc2b[t];
#pragma unroll 8
        for (int j = 0; j < NHID; j++) a += hid[j] * fc2w[j * 2 + t];
        logits[t] = a;
    }
    __syncthreads();
    if (t == 0) {
        float l0 = logits[0], l1 = logits[1];
        float mx = fmaxf(l0, l1);
        float lse = mx + logf(expf(l0 - mx) + expf(l1 - mx));
        out[g * 2 + 0] = l0 - lse;
        out[g * 2 + 1] = l1 - lse;
    }
}

// ---------------- launcher ----------------------------------------------------
extern "C" void kernel_launch(void* const* d_in, const int* in_sizes, int n_in,
                              void* d_out, int out_size)
{
    const float* x     = (const float*)d_in[0];
    const int*   ei    = (const int*)d_in[1];
    const int*   batch = (const int*)d_in[2];
    const float* W1    = (const float*)d_in[3];
    const float* as1   = (const float*)d_in[4];
    const float* ad1   = (const float*)d_in[5];
    const float* b1    = (const float*)d_in[6];
    const float* W2    = (const float*)d_in[7];
    const float* as2   = (const float*)d_in[8];
    const float* ad2   = (const float*)d_in[9];
    const float* b2    = (const float*)d_in[10];
    const float* fc1w  = (const float*)d_in[11];
    const float* fc1b  = (const float*)d_in[12];
    const float* fc2w  = (const float*)d_in[13];
    const float* fc2b  = (const float*)d_in[14];
    float* out = (float*)d_out;

    float* xw;  cudaGetSymbolAddress((void**)&xw,  g_xw);
    float* h;   cudaGetSymbolAddress((void**)&h,   g_h);
    __nv_bfloat16 *h1h, *h1l, *w1h, *w1l, *w2h, *w2l;
    cudaGetSymbolAddress((void**)&h1h, g_h1h);
    cudaGetSymbolAddress((void**)&h1l, g_h1l);
    cudaGetSymbolAddress((void**)&w1h, g_w1h);
    cudaGetSymbolAddress((void**)&w1l, g_w1l);
    cudaGetSymbolAddress((void**)&w2h, g_w2h);
    cudaGetSymbolAddress((void**)&w2l, g_w2l);

    // --- dtype detect + CSR build ---
    k_detect_dtype<<<1, 128>>>(ei);
    k_init_counts<<<(N_NODES + 255) / 256, 256>>>();
    k_histogram<<<(N_EDGES + 255) / 256, 256>>>(ei);
    k_scan1<<<SCAN_NB, 256>>>();
    k_scan2<<<1, 256>>>();
    k_scan3<<<SCAN_NB, 256>>>();
    k_selfloop_fill<<<(N_NODES + 255) / 256, 256>>>();
    k_scatter<<<(N_EDGES + 255) / 256, 256>>>(ei);

    // --- weight prep ---
    k_conv_w<<<(IN_F * HID2 + 255) / 256, 256>>>(W1, IN_F, w1h, w1l);
    k_conv_w<<<(HID2 * HID2 + 255) / 256, 256>>>(W2, HID2, w2h, w2l);

    const int GEMM_GRID = (N_NODES + 127) / 128;   // 391
    const int WARP_GRID = (N_NODES * 32 + 255) / 256;

    // --- layer 1 ---
    k_gemm_mma<0><<<GEMM_GRID, 256>>>(x, nullptr, nullptr, w1h, w1l,
                                      N_NODES, IN_F, as1, ad1, xw);
    k_gat_agg<1><<<WARP_GRID, 256>>>(xw, b1, nullptr, h1h, h1l);

    // --- layer 2 ---
    k_gemm_mma<1><<<GEMM_GRID, 256>>>(nullptr, h1h, h1l, w2h, w2l,
                                      N_NODES, HID2, as2, ad2, xw);
    k_gat_agg<0><<<WARP_GRID, 256>>>(xw, b2, h, nullptr, nullptr);

    // --- pool + MLP + log_softmax ---
    k_pool_mlp<<<N_GRAPHS, HID2>>>(h, batch, fc1w, fc1b, fc2w, fc2b, out);
}

// round 5
// speedup vs baseline: 1.7217x; 1.2660x over previous
#include <cuda_runtime.h>
#include <cuda_bf16.h>
#include <cstdint>

#define N_NODES  50000
#define N_EDGES  800000
#define E_TOT    850000
#define IN_F     768
#define HID2     128
#define NHID     64
#define N_GRAPHS 128
#define SCAN_NB  ((N_NODES + 255) / 256)   // 196

// ---------------- scratch (device globals; no runtime allocation) ----------
__device__ float g_xw[(size_t)N_NODES * HID2];
__device__ float g_h [(size_t)N_NODES * HID2];
__device__ __nv_bfloat16 g_h1h[(size_t)N_NODES * HID2];
__device__ __nv_bfloat16 g_h1l[(size_t)N_NODES * HID2];
__device__ __nv_bfloat16 g_w1h[(size_t)HID2 * IN_F];   // W1^T hi  [128][768]
__device__ __nv_bfloat16 g_w1l[(size_t)HID2 * IN_F];
__device__ __nv_bfloat16 g_w2h[(size_t)HID2 * HID2];   // W2^T hi  [128][128]
__device__ __nv_bfloat16 g_w2l[(size_t)HID2 * HID2];
__device__ float g_es[N_NODES];
__device__ float g_ed[N_NODES];
__device__ int   g_rowptr[N_NODES + 1];
__device__ int   g_counts[N_NODES];
__device__ int   g_fill[N_NODES];
__device__ int   g_srcidx[E_TOT];
__device__ int   g_blksum[256];
__device__ int   g_is64;

// ---------------- dtype-adaptive index loads --------------------------------
__device__ __forceinline__ int edge_src(const int* ei, int e) {
    return g_is64 ? (int)((const long long*)ei)[e] : ei[e];
}
__device__ __forceinline__ int edge_dst(const int* ei, int e) {
    return g_is64 ? (int)((const long long*)ei)[(size_t)N_EDGES + e]
                  : ei[(size_t)N_EDGES + e];
}
__device__ __forceinline__ int batch_at(const int* b, int i) {
    return g_is64 ? (int)((const long long*)b)[i] : b[i];
}

__global__ void k_detect_dtype(const int* __restrict__ ei) {
    int t = threadIdx.x;
    int nz = (ei[2 * t + 1] != 0) ? 1 : 0;
    int any = __syncthreads_or(nz);
    if (t == 0) g_is64 = any ? 0 : 1;
}

// ---------------- math helpers ----------------------------------------------
__device__ __forceinline__ float selu_f(float x) {
    const float sc = 1.0507009873554805f, al = 1.6732632423543772f;
    return x > 0.f ? sc * x : sc * al * expm1f(x);
}
__device__ __forceinline__ float lrelu02(float x) { return x > 0.f ? x : 0.2f * x; }

__device__ __forceinline__ uint32_t pack_bf2(float a, float b) {
    __nv_bfloat162 p(__float2bfloat16(a), __float2bfloat16(b));
    return *(uint32_t*)&p;
}

// ---------------- CSR construction ------------------------------------------
__global__ void k_init_counts() {
    int i = blockIdx.x * blockDim.x + threadIdx.x;
    if (i < N_NODES) g_counts[i] = 1;
}
__global__ void k_histogram(const int* __restrict__ ei) {
    int e = blockIdx.x * blockDim.x + threadIdx.x;
    if (e < N_EDGES) atomicAdd(&g_counts[edge_dst(ei, e)], 1);
}
__global__ void k_scan1() {
    __shared__ int sh[256];
    int b = blockIdx.x, t = threadIdx.x;
    int idx = b * 256 + t;
    sh[t] = (idx < N_NODES) ? g_counts[idx] : 0;
    __syncthreads();
    for (int off = 128; off; off >>= 1) {
        if (t < off) sh[t] += sh[t + off];
        __syncthreads();
    }
    if (t == 0) g_blksum[b] = sh[0];
}
__global__ void k_scan2() {
    __shared__ int sh[256];
    int t = threadIdx.x;
    int v = (t < SCAN_NB) ? g_blksum[t] : 0;
    sh[t] = v;
    __syncthreads();
    for (int off = 1; off < 256; off <<= 1) {
        int add = (t >= off) ? sh[t - off] : 0;
        __syncthreads();
        sh[t] += add;
        __syncthreads();
    }
    if (t < SCAN_NB) g_blksum[t] = sh[t] - v;     // exclusive
    if (t == 255) g_rowptr[N_NODES] = sh[255];
}
__global__ void k_scan3() {
    __shared__ int sh[256];
    int b = blockIdx.x, t = threadIdx.x;
    int idx = b * 256 + t;
    int v = (idx < N_NODES) ? g_counts[idx] : 0;
    sh[t] = v;
    __syncthreads();
    for (int off = 1; off < 256; off <<= 1) {
        int add = (t >= off) ? sh[t - off] : 0;
        __syncthreads();
        sh[t] += add;
        __syncthreads();
    }
    if (idx < N_NODES) g_rowptr[idx] = g_blksum[b] + sh[t] - v;
}
__global__ void k_selfloop_fill() {
    int i = blockIdx.x * blockDim.x + threadIdx.x;
    if (i < N_NODES) {
        int p = g_rowptr[i];
        g_srcidx[p] = i;
        g_fill[i] = p + 1;
    }
}
__global__ void k_scatter(const int* __restrict__ ei) {
    int e = blockIdx.x * blockDim.x + threadIdx.x;
    if (e < N_EDGES) {
        int src = edge_src(ei, e);
        int dst = edge_dst(ei, e);
        g_srcidx[atomicAdd(&g_fill[dst], 1)] = src;
    }
}

// ---------------- weight transpose + bf16 hi/lo split -------------------------
__global__ void k_conv_w(const float* __restrict__ W, int K,
                         __nv_bfloat16* __restrict__ Th, __nv_bfloat16* __restrict__ Tl) {
    int idx = blockIdx.x * blockDim.x + threadIdx.x;
    if (idx >= K * HID2) return;
    int n = idx & (HID2 - 1), k = idx >> 7;
    float v = W[(size_t)k * HID2 + n];
    __nv_bfloat16 h = __float2bfloat16(v);
    Th[(size_t)n * K + k] = h;
    Tl[(size_t)n * K + k] = __float2bfloat16(v - __bfloat162float(h));
}

// ---------------- mma.sync bf16-split GEMM + fused attention scores ----------
// C[128,128] CTA tile, 8 warps (2 m-halves x 4 n-quarters), warp tile 64x32.
// ldmatrix fragment loads; register-staged GMEM prefetch pipeline.
__device__ __forceinline__ void mma16816(float* c, const uint32_t* a, const uint32_t* b) {
    asm volatile(
        "mma.sync.aligned.m16n8k16.row.col.f32.bf16.bf16.f32 "
        "{%0,%1,%2,%3}, {%4,%5,%6,%7}, {%8,%9}, {%0,%1,%2,%3};"
        : "+f"(c[0]), "+f"(c[1]), "+f"(c[2]), "+f"(c[3])
        : "r"(a[0]), "r"(a[1]), "r"(a[2]), "r"(a[3]), "r"(b[0]), "r"(b[1]));
}
#define LDMX4(r, addr) \
    asm volatile("ldmatrix.sync.aligned.m8n8.x4.shared.b16 {%0,%1,%2,%3}, [%4];" \
        : "=r"((r)[0]), "=r"((r)[1]), "=r"((r)[2]), "=r"((r)[3]) : "r"(addr))

__device__ __forceinline__ uint32_t smem_u32(const void* p) {
    uint32_t a;
    asm("{ .reg .u64 t; cvta.to.shared.u64 t, %1; cvt.u32.u64 %0, t; }"
        : "=r"(a) : "l"(p));
    return a;
}

#define APAD 40   // bf16 row stride (80B): conflict-free for ldmatrix phases

template <int AMODE>   // 0: A fp32 (convert on load), 1: A bf16 hi/lo pair
__global__ __launch_bounds__(256) void k_gemm_mma(
    const float* __restrict__ Af,
    const __nv_bfloat16* __restrict__ Abh, const __nv_bfloat16* __restrict__ Abl,
    const __nv_bfloat16* __restrict__ Bh,  const __nv_bfloat16* __restrict__ Bl,
    int M, int K,
    const float* __restrict__ a_s, const float* __restrict__ a_d,
    float* __restrict__ xw)
{
    __shared__ __align__(16) __nv_bfloat16 sAh[128][APAD], sAl[128][APAD];
    __shared__ __align__(16) __nv_bfloat16 sBh[128][APAD], sBl[128][APAD];
    __shared__ float s_es[128], s_ed[128];

    int tid = threadIdx.x, lane = tid & 31, w = tid >> 5;
    int wm = w & 1, wn = w >> 1;               // 2 x 4 warp grid
    int block_row = blockIdx.x * 128;
    int q = lane >> 2, qr = lane & 3;

    uint32_t bAh = smem_u32(&sAh[0][0]), bAl = smem_u32(&sAl[0][0]);
    uint32_t bBh = smem_u32(&sBh[0][0]), bBl = smem_u32(&sBl[0][0]);

    float acc[4][4][4];
#pragma unroll
    for (int i = 0; i < 4; i++)
#pragma unroll
        for (int j = 0; j < 4; j++)
#pragma unroll
            for (int v = 0; v < 4; v++) acc[i][j][v] = 0.f;

    // ---- GMEM prefetch registers ----
    float4 pAf[4];
    uint2  pAh[4], pAl[4], pBh[4], pBl[4];
    const int nchunks = K >> 5;

#define LOAD_GLB(c) do {                                                        \
    int _k0 = (c) << 5;                                                         \
    _Pragma("unroll")                                                           \
    for (int it = 0; it < 4; it++) {                                            \
        int idx = tid + it * 256;                                               \
        int row = idx >> 3, col = (idx & 7) * 4;                                \
        int grow = block_row + row;                                             \
        if (grow >= M) grow = M - 1;                                            \
        if (AMODE == 0) {                                                       \
            pAf[it] = *(const float4*)(Af + (size_t)grow * K + _k0 + col);      \
        } else {                                                                \
            pAh[it] = *(const uint2*)(Abh + (size_t)grow * K + _k0 + col);      \
            pAl[it] = *(const uint2*)(Abl + (size_t)grow * K + _k0 + col);      \
        }                                                                       \
        pBh[it] = *(const uint2*)(Bh + (size_t)row * K + _k0 + col);            \
        pBl[it] = *(const uint2*)(Bl + (size_t)row * K + _k0 + col);            \
    } } while (0)

#define STORE_SMEM() do {                                                       \
    _Pragma("unroll")                                                           \
    for (int it = 0; it < 4; it++) {                                            \
        int idx = tid + it * 256;                                               \
        int row = idx >> 3, col = (idx & 7) * 4;                                \
        if (AMODE == 0) {                                                       \
            float4 v = pAf[it];                                                 \
            uint2 uh, ul;                                                       \
            uh.x = pack_bf2(v.x, v.y); uh.y = pack_bf2(v.z, v.w);               \
            ul.x = pack_bf2(v.x - __bfloat162float(__float2bfloat16(v.x)),      \
                            v.y - __bfloat162float(__float2bfloat16(v.y)));     \
            ul.y = pack_bf2(v.z - __bfloat162float(__float2bfloat16(v.z)),      \
                            v.w - __bfloat162float(__float2bfloat16(v.w)));     \
            *(uint2*)&sAh[row][col] = uh;                                       \
            *(uint2*)&sAl[row][col] = ul;                                       \
        } else {                                                                \
            *(uint2*)&sAh[row][col] = pAh[it];                                  \
            *(uint2*)&sAl[row][col] = pAl[it];                                  \
        }                                                                       \
        *(uint2*)&sBh[row][col] = pBh[it];                                      \
        *(uint2*)&sBl[row][col] = pBl[it];                                      \
    } } while (0)

    LOAD_GLB(0);
    STORE_SMEM();
    __syncthreads();

    for (int c = 0; c < nchunks; c++) {
        if (c + 1 < nchunks) LOAD_GLB(c + 1);   // overlap with MMA below
#pragma unroll
        for (int ks = 0; ks < 32; ks += 16) {
            uint32_t ah[4][4], al[4][4];
#pragma unroll
            for (int i = 0; i < 4; i++) {
                int row = wm * 64 + i * 16 + (lane & 15);
                int col = ks + ((lane >> 4) << 3);
                uint32_t off = (uint32_t)(row * APAD + col) * 2;
                LDMX4(ah[i], bAh + off);
                LDMX4(al[i], bAl + off);
            }
#pragma unroll
            for (int jp = 0; jp < 2; jp++) {
                int nrow = wn * 32 + jp * 16 + ((lane >> 4) << 3) + (lane & 7);
                int col  = ks + (((lane >> 3) & 1) << 3);
                uint32_t off = (uint32_t)(nrow * APAD + col) * 2;
                uint32_t bh[4], bl[4];
                LDMX4(bh, bBh + off);
                LDMX4(bl, bBl + off);
#pragma unroll
                for (int i = 0; i < 4; i++) {
                    mma16816(acc[i][2 * jp],     ah[i], bh);
                    mma16816(acc[i][2 * jp],     ah[i], bl);
                    mma16816(acc[i][2 * jp],     al[i], bh);
                    mma16816(acc[i][2 * jp + 1], ah[i], bh + 2);
                    mma16816(acc[i][2 * jp + 1], ah[i], bl + 2);
                    mma16816(acc[i][2 * jp + 1], al[i], bh + 2);
                }
            }
        }
        __syncthreads();
        if (c + 1 < nchunks) {
            STORE_SMEM();
            __syncthreads();
        }
    }

    // ---- epilogue: store xw + fused es/ed ----
    if (tid < 128) { s_es[tid] = 0.f; s_ed[tid] = 0.f; }
    __syncthreads();

    float2 asv[4], adv[4];
#pragma unroll
    for (int j = 0; j < 4; j++) {
        int col = wn * 32 + j * 8 + qr * 2;
        asv[j] = *(const float2*)(a_s + col);
        adv[j] = *(const float2*)(a_d + col);
    }

#pragma unroll
    for (int i = 0; i < 4; i++) {
        int lrow = wm * 64 + i * 16 + q;
        int grow0 = block_row + lrow;
        int grow1 = grow0 + 8;
        float e0s = 0.f, e0d = 0.f, e1s = 0.f, e1d = 0.f;
#pragma unroll
        for (int j = 0; j < 4; j++) {
            int col = wn * 32 + j * 8 + qr * 2;
            float d0 = acc[i][j][0], d1 = acc[i][j][1];
            float d2 = acc[i][j][2], d3 = acc[i][j][3];
            if (grow0 < M) *(float2*)(xw + (size_t)grow0 * HID2 + col) = make_float2(d0, d1);
            if (grow1 < M) *(float2*)(xw + (size_t)grow1 * HID2 + col) = make_float2(d2, d3);
            e0s += d0 * asv[j].x + d1 * asv[j].y;
            e0d += d0 * adv[j].x + d1 * adv[j].y;
            e1s += d2 * asv[j].x + d3 * asv[j].y;
            e1d += d2 * adv[j].x + d3 * adv[j].y;
        }
#pragma unroll
        for (int off = 1; off < 4; off <<= 1) {
            e0s += __shfl_xor_sync(0xffffffffu, e0s, off);
            e0d += __shfl_xor_sync(0xffffffffu, e0d, off);
            e1s += __shfl_xor_sync(0xffffffffu, e1s, off);
            e1d += __shfl_xor_sync(0xffffffffu, e1d, off);
        }
        if (qr == 0) {
            atomicAdd(&s_es[lrow], e0s);
            atomicAdd(&s_ed[lrow], e0d);
            atomicAdd(&s_es[lrow + 8], e1s);
            atomicAdd(&s_ed[lrow + 8], e1d);
        }
    }
    __syncthreads();
    if (tid < 128) {
        int grow = block_row + tid;
        if (grow < M) {
            g_es[grow] = s_es[tid];
            g_ed[grow] = s_ed[tid];
        }
    }
}

// ---------------- GAT aggregation: single pass, unnormalized softmax ---------
// alpha_i = exp(e_i) / sum(exp(e_j)); scores ~N(0,sqrt(2)) so exp can't overflow.
// OUT==0: fp32 out; OUT==1: bf16 hi/lo pair out (feeds next tensor GEMM)
template <int OUT>
__global__ void k_gat_agg(const float* __restrict__ xw,
                          const float* __restrict__ bias,
                          float* __restrict__ out_f32,
                          __nv_bfloat16* __restrict__ oh,
                          __nv_bfloat16* __restrict__ ol)
{
    int node = (blockIdx.x * blockDim.x + threadIdx.x) >> 5;
    int lane = threadIdx.x & 31;
    if (node >= N_NODES) return;
    int beg = g_rowptr[node], end = g_rowptr[node + 1];
    float edv = g_ed[node];

    float ssum = 0.f;
    float4 acc = make_float4(0.f, 0.f, 0.f, 0.f);
    for (int base = beg; base < end; base += 32) {
        int i = base + lane;
        float alpha = 0.f;
        int sidx = 0;
        if (i < end) {
            sidx = g_srcidx[i];
            alpha = __expf(lrelu02(g_es[sidx] + edv));
        }
        ssum += alpha;
        int cnt = min(32, end - base);
        for (int j = 0; j < cnt; j++) {
            float a = __shfl_sync(0xffffffffu, alpha, j);
            int   s = __shfl_sync(0xffffffffu, sidx, j);
            float4 v = ((const float4*)(xw + (size_t)s * HID2))[lane];
            acc.x += a * v.x; acc.y += a * v.y; acc.z += a * v.z; acc.w += a * v.w;
        }
    }
#pragma unroll
    for (int o = 16; o; o >>= 1) ssum += __shfl_xor_sync(0xffffffffu, ssum, o);
    float inv = 1.f / ssum;

    float4 b4 = ((const float4*)bias)[lane];
    float r0 = selu_f(acc.x * inv + b4.x), r1 = selu_f(acc.y * inv + b4.y);
    float r2 = selu_f(acc.z * inv + b4.z), r3 = selu_f(acc.w * inv + b4.w);
    if (OUT == 0) {
        ((float4*)(out_f32 + (size_t)node * HID2))[lane] = make_float4(r0, r1, r2, r3);
    } else {
        size_t off = (size_t)node * HID2 + lane * 4;
        uint2 uh, ul;
        uh.x = pack_bf2(r0, r1);
        uh.y = pack_bf2(r2, r3);
        ul.x = pack_bf2(r0 - __bfloat162float(__float2bfloat16(r0)),
                        r1 - __bfloat162float(__float2bfloat16(r1)));
        ul.y = pack_bf2(r2 - __bfloat162float(__float2bfloat16(r2)),
                        r3 - __bfloat162float(__float2bfloat16(r3)));
        *(uint2*)(oh + off) = uh;
        *(uint2*)(ol + off) = ul;
    }
}

// ---------------- pool + MLP + log_softmax -----------------------------------
__device__ __forceinline__ int lb_batch(const int* b, int n, int v) {
    int lo = 0, hi = n;
    while (lo < hi) {
        int mid = (lo + hi) >> 1;
        if (batch_at(b, mid) < v) lo = mid + 1; else hi = mid;
    }
    return lo;
}

__global__ void k_pool_mlp(const float* __restrict__ h,
                           const int* __restrict__ batch,
                           const float* __restrict__ fc1w, const float* __restrict__ fc1b,
                           const float* __restrict__ fc2w, const float* __restrict__ fc2b,
                           float* __restrict__ out)
{
    int g = blockIdx.x, t = threadIdx.x;
    __shared__ float pooled[HID2];
    __shared__ float hid[NHID];
    __shared__ float logits[2];

    int lo = lb_batch(batch, N_NODES, g);
    int hi = lb_batch(batch, N_NODES, g + 1);
    float s = 0.f;
    for (int i = lo; i < hi; i++) s += h[(size_t)i * HID2 + t];
    pooled[t] = selu_f(s / (float)max(hi - lo, 1));
    __syncthreads();

    if (t < NHID) {
        float a = fc1b[t];
#pragma unroll 8
        for (int c = 0; c < HID2; c++) a += pooled[c] * fc1w[c * NHID + t];
        hid[t] = selu_f(a);
    }
    __syncthreads();
    if (t < 2) {
        float a = fc2b[t];
#pragma unroll 8
        for (int j = 0; j < NHID; j++) a += hid[j] * fc2w[j * 2 + t];
        logits[t] = a;
    }
    __syncthreads();
    if (t == 0) {
        float l0 = logits[0], l1 = logits[1];
        float mx = fmaxf(l0, l1);
        float lse = mx + logf(expf(l0 - mx) + expf(l1 - mx));
        out[g * 2 + 0] = l0 - lse;
        out[g * 2 + 1] = l1 - lse;
    }
}

// ---------------- launcher ----------------------------------------------------
extern "C" void kernel_launch(void* const* d_in, const int* in_sizes, int n_in,
                              void* d_out, int out_size)
{
    const float* x     = (const float*)d_in[0];
    const int*   ei    = (const int*)d_in[1];
    const int*   batch = (const int*)d_in[2];
    const float* W1    = (const float*)d_in[3];
    const float* as1   = (const float*)d_in[4];
    const float* ad1   = (const float*)d_in[5];
    const float* b1    = (const float*)d_in[6];
    const float* W2    = (const float*)d_in[7];
    const float* as2   = (const float*)d_in[8];
    const float* ad2   = (const float*)d_in[9];
    const float* b2    = (const float*)d_in[10];
    const float* fc1w  = (const float*)d_in[11];
    const float* fc1b  = (const float*)d_in[12];
    const float* fc2w  = (const float*)d_in[13];
    const float* fc2b  = (const float*)d_in[14];
    float* out = (float*)d_out;

    float* xw;  cudaGetSymbolAddress((void**)&xw,  g_xw);
    float* h;   cudaGetSymbolAddress((void**)&h,   g_h);
    __nv_bfloat16 *h1h, *h1l, *w1h, *w1l, *w2h, *w2l;
    cudaGetSymbolAddress((void**)&h1h, g_h1h);
    cudaGetSymbolAddress((void**)&h1l, g_h1l);
    cudaGetSymbolAddress((void**)&w1h, g_w1h);
    cudaGetSymbolAddress((void**)&w1l, g_w1l);
    cudaGetSymbolAddress((void**)&w2h, g_w2h);
    cudaGetSymbolAddress((void**)&w2l, g_w2l);

    // --- dtype detect + CSR build ---
    k_detect_dtype<<<1, 128>>>(ei);
    k_init_counts<<<(N_NODES + 255) / 256, 256>>>();
    k_histogram<<<(N_EDGES + 255) / 256, 256>>>(ei);
    k_scan1<<<SCAN_NB, 256>>>();
    k_scan2<<<1, 256>>>();
    k_scan3<<<SCAN_NB, 256>>>();
    k_selfloop_fill<<<(N_NODES + 255) / 256, 256>>>();
    k_scatter<<<(N_EDGES + 255) / 256, 256>>>(ei);

    // --- weight prep ---
    k_conv_w<<<(IN_F * HID2 + 255) / 256, 256>>>(W1, IN_F, w1h, w1l);
    k_conv_w<<<(HID2 * HID2 + 255) / 256, 256>>>(W2, HID2, w2h, w2l);

    const int GEMM_GRID = (N_NODES + 127) / 128;   // 391
    const int WARP_GRID = (N_NODES * 32 + 255) / 256;

    // --- layer 1 ---
    k_gemm_mma<0><<<GEMM_GRID, 256>>>(x, nullptr, nullptr, w1h, w1l,
                                      N_NODES, IN_F, as1, ad1, xw);
    k_gat_agg<1><<<WARP_GRID, 256>>>(xw, b1, nullptr, h1h, h1l);

    // --- layer 2 ---
    k_gemm_mma<1><<<GEMM_GRID, 256>>>(nullptr, h1h, h1l, w2h, w2l,
                                      N_NODES, HID2, as2, ad2, xw);
    k_gat_agg<0><<<WARP_GRID, 256>>>(xw, b2, h, nullptr, nullptr);

    // --- pool + MLP + log_softmax ---
    k_pool_mlp<<<N_GRAPHS, HID2>>>(h, batch, fc1w, fc1b, fc2w, fc2b, out);
}

// round 6
// speedup vs baseline: 1.8577x; 1.0790x over previous
#include <cuda_runtime.h>
#include <cuda_bf16.h>
#include <cstdint>

#define N_NODES  50000
#define N_EDGES  800000
#define E_TOT    850000
#define IN_F     768
#define HID2     128
#define NHID     64
#define N_GRAPHS 128
#define SCAN_NB  ((N_NODES + 255) / 256)   // 196
#define SCAT_NB  64                        // grid-stride scatter blocks in gemm1

// ---------------- scratch (device globals; no runtime allocation) ----------
__device__ float g_xw[(size_t)N_NODES * HID2];
__device__ float g_h [(size_t)N_NODES * HID2];
__device__ __nv_bfloat16 g_h1h[(size_t)N_NODES * HID2];
__device__ __nv_bfloat16 g_h1l[(size_t)N_NODES * HID2];
__device__ __nv_bfloat16 g_w1h[(size_t)HID2 * IN_F];
__device__ __nv_bfloat16 g_w1l[(size_t)HID2 * IN_F];
__device__ __nv_bfloat16 g_w2h[(size_t)HID2 * HID2];
__device__ __nv_bfloat16 g_w2l[(size_t)HID2 * HID2];
__device__ float g_es[N_NODES];
__device__ float g_ed[N_NODES];
__device__ int   g_rowptr[N_NODES + 1];
__device__ int   g_counts[N_NODES];
__device__ int   g_fill[N_NODES];
__device__ int   g_srcidx[E_TOT];
__device__ int   g_blksum[256];
__device__ int   g_is64;

// ---------------- helpers ----------------------------------------------------
__device__ __forceinline__ float selu_f(float x) {
    const float sc = 1.0507009873554805f, al = 1.6732632423543772f;
    return x > 0.f ? sc * x : sc * al * expm1f(x);
}
__device__ __forceinline__ float lrelu02(float x) { return x > 0.f ? x : 0.2f * x; }
__device__ __forceinline__ uint32_t pack_bf2(float a, float b) {
    __nv_bfloat162 p(__float2bfloat16(a), __float2bfloat16(b));
    return *(uint32_t*)&p;
}
__device__ __forceinline__ int batch_at(const int* b, int i) {
    return g_is64 ? (int)((const long long*)b)[i] : b[i];
}

// ---------------- prep: counts init + weight transpose/split -----------------
// blocks [0,196): init counts; [196,580): W1 conv; [580,644): W2 conv
__global__ void k_prep(const float* __restrict__ W1, const float* __restrict__ W2) {
    int b = blockIdx.x, t = threadIdx.x;
    if (b < SCAN_NB) {
        int i = b * 256 + t;
        if (i < N_NODES) g_counts[i] = 1;       // self loop pre-counted
    } else if (b < SCAN_NB + 384) {
        int idx = (b - SCAN_NB) * 256 + t;      // IN_F*HID2 = 98304
        int n = idx & (HID2 - 1), k = idx >> 7;
        float v = W1[(size_t)k * HID2 + n];
        __nv_bfloat16 hb = __float2bfloat16(v);
        g_w1h[(size_t)n * IN_F + k] = hb;
        g_w1l[(size_t)n * IN_F + k] = __float2bfloat16(v - __bfloat162float(hb));
    } else {
        int idx = (b - SCAN_NB - 384) * 256 + t;  // HID2*HID2 = 16384
        int n = idx & (HID2 - 1), k = idx >> 7;
        float v = W2[(size_t)k * HID2 + n];
        __nv_bfloat16 hb = __float2bfloat16(v);
        g_w2h[(size_t)n * HID2 + k] = hb;
        g_w2l[(size_t)n * HID2 + k] = __float2bfloat16(v - __bfloat162float(hb));
    }
}

// ---------------- histogram with inline dtype detect -------------------------
__global__ void k_histogram(const int* __restrict__ ei) {
    __shared__ int s64;
    if (threadIdx.x < 32) {
        int nz = (ei[2 * threadIdx.x + 1] != 0) ? 1 : 0;
        uint32_t bal = __ballot_sync(0xffffffffu, nz);
        if (threadIdx.x == 0) s64 = (bal == 0u) ? 1 : 0;
    }
    __syncthreads();
    int is64 = s64;
    if (blockIdx.x == 0 && threadIdx.x == 0) g_is64 = is64;   // for later kernels
    int e = blockIdx.x * blockDim.x + threadIdx.x;
    if (e < N_EDGES) {
        int dst = is64 ? (int)((const long long*)ei)[(size_t)N_EDGES + e]
                       : ei[(size_t)N_EDGES + e];
        atomicAdd(&g_counts[dst], 1);
    }
}

// ---------------- 3-phase scan ------------------------------------------------
__global__ void k_scan1() {
    __shared__ int sh[256];
    int b = blockIdx.x, t = threadIdx.x;
    int idx = b * 256 + t;
    sh[t] = (idx < N_NODES) ? g_counts[idx] : 0;
    __syncthreads();
    for (int off = 128; off; off >>= 1) {
        if (t < off) sh[t] += sh[t + off];
        __syncthreads();
    }
    if (t == 0) g_blksum[b] = sh[0];
}
__global__ void k_scan2() {
    __shared__ int sh[256];
    int t = threadIdx.x;
    int v = (t < SCAN_NB) ? g_blksum[t] : 0;
    sh[t] = v;
    __syncthreads();
    for (int off = 1; off < 256; off <<= 1) {
        int add = (t >= off) ? sh[t - off] : 0;
        __syncthreads();
        sh[t] += add;
        __syncthreads();
    }
    if (t < SCAN_NB) g_blksum[t] = sh[t] - v;
    if (t == 255) g_rowptr[N_NODES] = sh[255];
}
__global__ void k_scan3() {   // local scan + self-loop fill fused
    __shared__ int sh[256];
    int b = blockIdx.x, t = threadIdx.x;
    int idx = b * 256 + t;
    int v = (idx < N_NODES) ? g_counts[idx] : 0;
    sh[t] = v;
    __syncthreads();
    for (int off = 1; off < 256; off <<= 1) {
        int add = (t >= off) ? sh[t - off] : 0;
        __syncthreads();
        sh[t] += add;
        __syncthreads();
    }
    if (idx < N_NODES) {
        int p = g_blksum[b] + sh[t] - v;
        g_rowptr[idx] = p;
        g_srcidx[p] = idx;    // self loop first
        g_fill[idx] = p + 1;
    }
}

// ---------------- mma.sync bf16-split GEMM (double-buffered) -----------------
__device__ __forceinline__ void mma16816(float* c, const uint32_t* a, const uint32_t* b) {
    asm volatile(
        "mma.sync.aligned.m16n8k16.row.col.f32.bf16.bf16.f32 "
        "{%0,%1,%2,%3}, {%4,%5,%6,%7}, {%8,%9}, {%0,%1,%2,%3};"
        : "+f"(c[0]), "+f"(c[1]), "+f"(c[2]), "+f"(c[3])
        : "r"(a[0]), "r"(a[1]), "r"(a[2]), "r"(a[3]), "r"(b[0]), "r"(b[1]));
}
#define LDMX4(r, addr) \
    asm volatile("ldmatrix.sync.aligned.m8n8.x4.shared.b16 {%0,%1,%2,%3}, [%4];" \
        : "=r"((r)[0]), "=r"((r)[1]), "=r"((r)[2]), "=r"((r)[3]) : "r"(addr))
__device__ __forceinline__ uint32_t smem_u32(const void* p) {
    uint32_t a;
    asm("{ .reg .u64 t; cvta.to.shared.u64 t, %1; cvt.u32.u64 %0, t; }"
        : "=r"(a) : "l"(p));
    return a;
}

#define APAD   40            // bf16 row stride (80B), conflict-free ldmatrix
#define TILE_B 10240         // one 128x40 bf16 tile
#define BUF_B  (4 * TILE_B)  // Ah,Al,Bh,Bl per buffer
#define GEMM_DSMEM (2 * BUF_B)   // 81920

template <int AMODE>   // 0: A fp32 (convert on load), 1: A bf16 hi/lo pair
__global__ __launch_bounds__(256) void k_gemm_mma(
    const float* __restrict__ Af,
    const __nv_bfloat16* __restrict__ Abh, const __nv_bfloat16* __restrict__ Abl,
    const __nv_bfloat16* __restrict__ Bh,  const __nv_bfloat16* __restrict__ Bl,
    int M, int K,
    const float* __restrict__ a_s, const float* __restrict__ a_d,
    float* __restrict__ xw,
    int gemm_blocks, const int* __restrict__ ei)
{
    // ---- extra blocks: grid-stride edge scatter (overlapped with GEMM) ----
    if ((int)blockIdx.x >= gemm_blocks) {
        int bid = blockIdx.x - gemm_blocks;
        int is64 = g_is64;
        for (int e = bid * 256 + (int)threadIdx.x; e < N_EDGES; e += SCAT_NB * 256) {
            int src, dst;
            if (is64) {
                src = (int)((const long long*)ei)[e];
                dst = (int)((const long long*)ei)[(size_t)N_EDGES + e];
            } else {
                src = ei[e];
                dst = ei[(size_t)N_EDGES + e];
            }
            g_srcidx[atomicAdd(&g_fill[dst], 1)] = src;
        }
        return;
    }

    extern __shared__ __align__(16) char dsm[];
    __shared__ float s_es[128], s_ed[128];

    int tid = threadIdx.x, lane = tid & 31, w = tid >> 5;
    int wm = w & 1, wn = w >> 1;
    int block_row = blockIdx.x * 128;
    int q = lane >> 2, qr = lane & 3;
    uint32_t base = smem_u32(dsm);

    float acc[4][4][4];
#pragma unroll
    for (int i = 0; i < 4; i++)
#pragma unroll
        for (int j = 0; j < 4; j++)
#pragma unroll
            for (int v = 0; v < 4; v++) acc[i][j][v] = 0.f;

    float4 pAf[4];
    uint2  pAh[4], pAl[4], pBh[4], pBl[4];
    const int nchunks = K >> 5;

#define LOAD_GLB(c) do {                                                        \
    int _k0 = (c) << 5;                                                         \
    _Pragma("unroll")                                                           \
    for (int it = 0; it < 4; it++) {                                            \
        int idx = tid + it * 256;                                               \
        int row = idx >> 3, col = (idx & 7) * 4;                                \
        int grow = block_row + row;                                             \
        if (grow >= M) grow = M - 1;                                            \
        if (AMODE == 0) {                                                       \
            pAf[it] = *(const float4*)(Af + (size_t)grow * K + _k0 + col);      \
        } else {                                                                \
            pAh[it] = *(const uint2*)(Abh + (size_t)grow * K + _k0 + col);      \
            pAl[it] = *(const uint2*)(Abl + (size_t)grow * K + _k0 + col);      \
        }                                                                       \
        pBh[it] = *(const uint2*)(Bh + (size_t)row * K + _k0 + col);            \
        pBl[it] = *(const uint2*)(Bl + (size_t)row * K + _k0 + col);            \
    } } while (0)

#define STORE_SMEM(buf) do {                                                    \
    char* _db = dsm + (buf) * BUF_B;                                            \
    _Pragma("unroll")                                                           \
    for (int it = 0; it < 4; it++) {                                            \
        int idx = tid + it * 256;                                               \
        int row = idx >> 3, col = (idx & 7) * 4;                                \
        uint32_t _o = (uint32_t)(row * APAD + col) * 2;                         \
        if (AMODE == 0) {                                                       \
            float4 v = pAf[it];                                                 \
            uint2 uh, ul;                                                       \
            uh.x = pack_bf2(v.x, v.y); uh.y = pack_bf2(v.z, v.w);               \
            ul.x = pack_bf2(v.x - __bfloat162float(__float2bfloat16(v.x)),      \
                            v.y - __bfloat162float(__float2bfloat16(v.y)));     \
            ul.y = pack_bf2(v.z - __bfloat162float(__float2bfloat16(v.z)),      \
                            v.w - __bfloat162float(__float2bfloat16(v.w)));     \
            *(uint2*)(_db + _o) = uh;                                           \
            *(uint2*)(_db + TILE_B + _o) = ul;                                  \
        } else {                                                                \
            *(uint2*)(_db + _o) = pAh[it];                                      \
            *(uint2*)(_db + TILE_B + _o) = pAl[it];                             \
        }                                                                       \
        *(uint2*)(_db + 2 * TILE_B + _o) = pBh[it];                             \
        *(uint2*)(_db + 3 * TILE_B + _o) = pBl[it];                             \
    } } while (0)

    LOAD_GLB(0);
    STORE_SMEM(0);
    __syncthreads();

    for (int c = 0; c < nchunks; c++) {
        int cb = c & 1;
        if (c + 1 < nchunks) LOAD_GLB(c + 1);
        uint32_t bAh = base + cb * BUF_B;
        uint32_t bAl = bAh + TILE_B, bBh = bAh + 2 * TILE_B, bBl = bAh + 3 * TILE_B;
#pragma unroll
        for (int ks = 0; ks < 32; ks += 16) {
            uint32_t ah[4][4], al[4][4];
#pragma unroll
            for (int i = 0; i < 4; i++) {
                int row = wm * 64 + i * 16 + (lane & 15);
                int col = ks + ((lane >> 4) << 3);
                uint32_t off = (uint32_t)(row * APAD + col) * 2;
                LDMX4(ah[i], bAh + off);
                LDMX4(al[i], bAl + off);
            }
#pragma unroll
            for (int jp = 0; jp < 2; jp++) {
                int nrow = wn * 32 + jp * 16 + ((lane >> 4) << 3) + (lane & 7);
                int col  = ks + (((lane >> 3) & 1) << 3);
                uint32_t off = (uint32_t)(nrow * APAD + col) * 2;
                uint32_t bh[4], bl[4];
                LDMX4(bh, bBh + off);
                LDMX4(bl, bBl + off);
#pragma unroll
                for (int i = 0; i < 4; i++) {
                    mma16816(acc[i][2 * jp],     ah[i], bh);
                    mma16816(acc[i][2 * jp],     ah[i], bl);
                    mma16816(acc[i][2 * jp],     al[i], bh);
                    mma16816(acc[i][2 * jp + 1], ah[i], bh + 2);
                    mma16816(acc[i][2 * jp + 1], ah[i], bl + 2);
                    mma16816(acc[i][2 * jp + 1], al[i], bh + 2);
                }
            }
        }
        if (c + 1 < nchunks) STORE_SMEM(!cb);   // other buffer: no conflict
        __syncthreads();
    }

    // ---- epilogue: store xw + fused es/ed ----
    if (tid < 128) { s_es[tid] = 0.f; s_ed[tid] = 0.f; }
    __syncthreads();

    float2 asv[4], adv[4];
#pragma unroll
    for (int j = 0; j < 4; j++) {
        int col = wn * 32 + j * 8 + qr * 2;
        asv[j] = *(const float2*)(a_s + col);
        adv[j] = *(const float2*)(a_d + col);
    }
#pragma unroll
    for (int i = 0; i < 4; i++) {
        int lrow = wm * 64 + i * 16 + q;
        int grow0 = block_row + lrow;
        int grow1 = grow0 + 8;
        float e0s = 0.f, e0d = 0.f, e1s = 0.f, e1d = 0.f;
#pragma unroll
        for (int j = 0; j < 4; j++) {
            int col = wn * 32 + j * 8 + qr * 2;
            float d0 = acc[i][j][0], d1 = acc[i][j][1];
            float d2 = acc[i][j][2], d3 = acc[i][j][3];
            if (grow0 < M) *(float2*)(xw + (size_t)grow0 * HID2 + col) = make_float2(d0, d1);
            if (grow1 < M) *(float2*)(xw + (size_t)grow1 * HID2 + col) = make_float2(d2, d3);
            e0s += d0 * asv[j].x + d1 * asv[j].y;
            e0d += d0 * adv[j].x + d1 * adv[j].y;
            e1s += d2 * asv[j].x + d3 * asv[j].y;
            e1d += d2 * adv[j].x + d3 * adv[j].y;
        }
#pragma unroll
        for (int off = 1; off < 4; off <<= 1) {
            e0s += __shfl_xor_sync(0xffffffffu, e0s, off);
            e0d += __shfl_xor_sync(0xffffffffu, e0d, off);
            e1s += __shfl_xor_sync(0xffffffffu, e1s, off);
            e1d += __shfl_xor_sync(0xffffffffu, e1d, off);
        }
        if (qr == 0) {
            atomicAdd(&s_es[lrow], e0s);
            atomicAdd(&s_ed[lrow], e0d);
            atomicAdd(&s_es[lrow + 8], e1s);
            atomicAdd(&s_ed[lrow + 8], e1d);
        }
    }
    __syncthreads();
    if (tid < 128) {
        int grow = block_row + tid;
        if (grow < M) {
            g_es[grow] = s_es[tid];
            g_ed[grow] = s_ed[tid];
        }
    }
}

// ---------------- GAT aggregation: single pass, unnormalized softmax ---------
template <int OUT>
__global__ void k_gat_agg(const float* __restrict__ xw,
                          const float* __restrict__ bias,
                          float* __restrict__ out_f32,
                          __nv_bfloat16* __restrict__ oh,
                          __nv_bfloat16* __restrict__ ol)
{
    int node = (blockIdx.x * blockDim.x + threadIdx.x) >> 5;
    int lane = threadIdx.x & 31;
    if (node >= N_NODES) return;
    int beg = g_rowptr[node], end = g_rowptr[node + 1];
    float edv = g_ed[node];

    float ssum = 0.f;
    float4 acc = make_float4(0.f, 0.f, 0.f, 0.f);
    for (int base = beg; base < end; base += 32) {
        int i = base + lane;
        float alpha = 0.f;
        int sidx = 0;
        if (i < end) {
            sidx = g_srcidx[i];
            alpha = __expf(lrelu02(g_es[sidx] + edv));
        }
        ssum += alpha;
        int cnt = min(32, end - base);
        for (int j = 0; j < cnt; j++) {
            float a = __shfl_sync(0xffffffffu, alpha, j);
            int   s = __shfl_sync(0xffffffffu, sidx, j);
            float4 v = ((const float4*)(xw + (size_t)s * HID2))[lane];
            acc.x += a * v.x; acc.y += a * v.y; acc.z += a * v.z; acc.w += a * v.w;
        }
    }
#pragma unroll
    for (int o = 16; o; o >>= 1) ssum += __shfl_xor_sync(0xffffffffu, ssum, o);
    float inv = 1.f / ssum;

    float4 b4 = ((const float4*)bias)[lane];
    float r0 = selu_f(acc.x * inv + b4.x), r1 = selu_f(acc.y * inv + b4.y);
    float r2 = selu_f(acc.z * inv + b4.z), r3 = selu_f(acc.w * inv + b4.w);
    if (OUT == 0) {
        ((float4*)(out_f32 + (size_t)node * HID2))[lane] = make_float4(r0, r1, r2, r3);
    } else {
        size_t off = (size_t)node * HID2 + lane * 4;
        uint2 uh, ul;
        uh.x = pack_bf2(r0, r1);
        uh.y = pack_bf2(r2, r3);
        ul.x = pack_bf2(r0 - __bfloat162float(__float2bfloat16(r0)),
                        r1 - __bfloat162float(__float2bfloat16(r1)));
        ul.y = pack_bf2(r2 - __bfloat162float(__float2bfloat16(r2)),
                        r3 - __bfloat162float(__float2bfloat16(r3)));
        *(uint2*)(oh + off) = uh;
        *(uint2*)(ol + off) = ul;
    }
}

// ---------------- pool + MLP + log_softmax -----------------------------------
__device__ __forceinline__ int lb_batch(const int* b, int n, int v) {
    int lo = 0, hi = n;
    while (lo < hi) {
        int mid = (lo + hi) >> 1;
        if (batch_at(b, mid) < v) lo = mid + 1; else hi = mid;
    }
    return lo;
}

__global__ void k_pool_mlp(const float* __restrict__ h,
                           const int* __restrict__ batch,
                           const float* __restrict__ fc1w, const float* __restrict__ fc1b,
                           const float* __restrict__ fc2w, const float* __restrict__ fc2b,
                           float* __restrict__ out)
{
    int g = blockIdx.x, t = threadIdx.x;
    __shared__ float pooled[HID2];
    __shared__ float hid[NHID];
    __shared__ float logits[2];

    int lo = lb_batch(batch, N_NODES, g);
    int hi = lb_batch(batch, N_NODES, g + 1);
    float s = 0.f;
    for (int i = lo; i < hi; i++) s += h[(size_t)i * HID2 + t];
    pooled[t] = selu_f(s / (float)max(hi - lo, 1));
    __syncthreads();

    if (t < NHID) {
        float a = fc1b[t];
#pragma unroll 8
        for (int c = 0; c < HID2; c++) a += pooled[c] * fc1w[c * NHID + t];
        hid[t] = selu_f(a);
    }
    __syncthreads();
    if (t < 2) {
        float a = fc2b[t];
#pragma unroll 8
        for (int j = 0; j < NHID; j++) a += hid[j] * fc2w[j * 2 + t];
        logits[t] = a;
    }
    __syncthreads();
    if (t == 0) {
        float l0 = logits[0], l1 = logits[1];
        float mx = fmaxf(l0, l1);
        float lse = mx + logf(expf(l0 - mx) + expf(l1 - mx));
        out[g * 2 + 0] = l0 - lse;
        out[g * 2 + 1] = l1 - lse;
    }
}

// ---------------- launcher ----------------------------------------------------
extern "C" void kernel_launch(void* const* d_in, const int* in_sizes, int n_in,
                              void* d_out, int out_size)
{
    const float* x     = (const float*)d_in[0];
    const int*   ei    = (const int*)d_in[1];
    const int*   batch = (const int*)d_in[2];
    const float* W1    = (const float*)d_in[3];
    const float* as1   = (const float*)d_in[4];
    const float* ad1   = (const float*)d_in[5];
    const float* b1    = (const float*)d_in[6];
    const float* W2    = (const float*)d_in[7];
    const float* as2   = (const float*)d_in[8];
    const float* ad2   = (const float*)d_in[9];
    const float* b2    = (const float*)d_in[10];
    const float* fc1w  = (const float*)d_in[11];
    const float* fc1b  = (const float*)d_in[12];
    const float* fc2w  = (const float*)d_in[13];
    const float* fc2b  = (const float*)d_in[14];
    float* out = (float*)d_out;

    float* xw;  cudaGetSymbolAddress((void**)&xw,  g_xw);
    float* h;   cudaGetSymbolAddress((void**)&h,   g_h);
    __nv_bfloat16 *h1h, *h1l, *w1h, *w1l, *w2h, *w2l;
    cudaGetSymbolAddress((void**)&h1h, g_h1h);
    cudaGetSymbolAddress((void**)&h1l, g_h1l);
    cudaGetSymbolAddress((void**)&w1h, g_w1h);
    cudaGetSymbolAddress((void**)&w1l, g_w1l);
    cudaGetSymbolAddress((void**)&w2h, g_w2h);
    cudaGetSymbolAddress((void**)&w2l, g_w2l);

    cudaFuncSetAttribute(k_gemm_mma<0>, cudaFuncAttributeMaxDynamicSharedMemorySize, GEMM_DSMEM);
    cudaFuncSetAttribute(k_gemm_mma<1>, cudaFuncAttributeMaxDynamicSharedMemorySize, GEMM_DSMEM);

    const int GEMM_GRID = (N_NODES + 127) / 128;   // 391
    const int WARP_GRID = (N_NODES * 32 + 255) / 256;

    // --- prep (counts + weight split) + CSR counting/scan ---
    k_prep<<<SCAN_NB + 384 + 64, 256>>>(W1, W2);
    k_histogram<<<(N_EDGES + 255) / 256, 256>>>(ei);
    k_scan1<<<SCAN_NB, 256>>>();
    k_scan2<<<1, 256>>>();
    k_scan3<<<SCAN_NB, 256>>>();

    // --- layer 1 GEMM with edge-scatter overlapped as extra blocks ---
    k_gemm_mma<0><<<GEMM_GRID + SCAT_NB, 256, GEMM_DSMEM>>>(
        x, nullptr, nullptr, w1h, w1l, N_NODES, IN_F, as1, ad1, xw, GEMM_GRID, ei);
    k_gat_agg<1><<<WARP_GRID, 256>>>(xw, b1, nullptr, h1h, h1l);

    // --- layer 2 ---
    k_gemm_mma<1><<<GEMM_GRID, 256, GEMM_DSMEM>>>(
        nullptr, h1h, h1l, w2h, w2l, N_NODES, HID2, as2, ad2, xw, GEMM_GRID, nullptr);
    k_gat_agg<0><<<WARP_GRID, 256>>>(xw, b2, h, nullptr, nullptr);

    // --- pool + MLP + log_softmax ---
    k_pool_mlp<<<N_GRAPHS, HID2>>>(h, batch, fc1w, fc1b, fc2w, fc2b, out);
}

// round 7
// speedup vs baseline: 1.9538x; 1.0517x over previous
#include <cuda_runtime.h>
#include <cuda_bf16.h>
#include <cstdint>

#define N_NODES  50000
#define N_EDGES  800000
#define E_TOT    850000
#define IN_F     768
#define HID2     128
#define NHID     64
#define N_GRAPHS 128
#define SCAN_NB  ((N_NODES + 255) / 256)   // 196
#define HIST_NB  ((N_EDGES + 255) / 256)   // 3125
#define SCAT_NB  64                        // grid-stride scatter blocks in gemm1

// ---------------- scratch (device globals; no runtime allocation) ----------
__device__ __nv_bfloat16 g_xwb[(size_t)N_NODES * HID2];  // GEMM out, bf16 (gather payload)
__device__ float g_h [(size_t)N_NODES * HID2];
__device__ __nv_bfloat16 g_h1h[(size_t)N_NODES * HID2];
__device__ __nv_bfloat16 g_h1l[(size_t)N_NODES * HID2];
__device__ __nv_bfloat16 g_w1h[(size_t)HID2 * IN_F];
__device__ __nv_bfloat16 g_w1l[(size_t)HID2 * IN_F];
__device__ __nv_bfloat16 g_w2h[(size_t)HID2 * HID2];
__device__ __nv_bfloat16 g_w2l[(size_t)HID2 * HID2];
__device__ float g_es[N_NODES];
__device__ float g_ed[N_NODES];
__device__ int   g_rowptr[N_NODES + 1];
__device__ int   g_counts[N_NODES];   // zero-init at load; scan3 re-zeroes each run
__device__ int   g_fill[N_NODES];
__device__ int   g_srcidx[E_TOT];
__device__ int   g_blksum[256];
__device__ int   g_is64;

// ---------------- helpers ----------------------------------------------------
__device__ __forceinline__ float selu_f(float x) {
    const float sc = 1.0507009873554805f, al = 1.6732632423543772f;
    return x > 0.f ? sc * x : sc * al * expm1f(x);
}
__device__ __forceinline__ float lrelu02(float x) { return x > 0.f ? x : 0.2f * x; }
__device__ __forceinline__ uint32_t pack_bf2(float a, float b) {
    __nv_bfloat162 p(__float2bfloat16(a), __float2bfloat16(b));
    return *(uint32_t*)&p;
}
__device__ __forceinline__ int batch_at(const int* b, int i) {
    return g_is64 ? (int)((const long long*)b)[i] : b[i];
}

// ---------------- prep + histogram (merged; counts pre-zeroed) ---------------
// blocks [0,3125): edge histogram (with inline dtype detect)
// blocks [3125,3509): W1 transpose/split ; [3509,3573): W2 transpose/split
__global__ void k_histprep(const int* __restrict__ ei,
                           const float* __restrict__ W1, const float* __restrict__ W2) {
    int b = blockIdx.x, t = threadIdx.x;
    if (b < HIST_NB) {
        __shared__ int s64;
        if (t < 32) {
            int nz = (ei[2 * t + 1] != 0) ? 1 : 0;
            uint32_t bal = __ballot_sync(0xffffffffu, nz);
            if (t == 0) s64 = (bal == 0u) ? 1 : 0;
        }
        __syncthreads();
        int is64 = s64;
        if (b == 0 && t == 0) g_is64 = is64;
        int e = b * 256 + t;
        if (e < N_EDGES) {
            int dst = is64 ? (int)((const long long*)ei)[(size_t)N_EDGES + e]
                           : ei[(size_t)N_EDGES + e];
            atomicAdd(&g_counts[dst], 1);
        }
    } else if (b < HIST_NB + 384) {
        int idx = (b - HIST_NB) * 256 + t;      // IN_F*HID2 = 98304
        int n = idx & (HID2 - 1), k = idx >> 7;
        float v = W1[(size_t)k * HID2 + n];
        __nv_bfloat16 hb = __float2bfloat16(v);
        g_w1h[(size_t)n * IN_F + k] = hb;
        g_w1l[(size_t)n * IN_F + k] = __float2bfloat16(v - __bfloat162float(hb));
    } else {
        int idx = (b - HIST_NB - 384) * 256 + t;  // HID2*HID2 = 16384
        int n = idx & (HID2 - 1), k = idx >> 7;
        float v = W2[(size_t)k * HID2 + n];
        __nv_bfloat16 hb = __float2bfloat16(v);
        g_w2h[(size_t)n * HID2 + k] = hb;
        g_w2l[(size_t)n * HID2 + k] = __float2bfloat16(v - __bfloat162float(hb));
    }
}

// ---------------- 3-phase scan over (counts + 1 self loop) -------------------
__global__ void k_scan1() {
    __shared__ int sh[256];
    int b = blockIdx.x, t = threadIdx.x;
    int idx = b * 256 + t;
    sh[t] = (idx < N_NODES) ? g_counts[idx] + 1 : 0;
    __syncthreads();
    for (int off = 128; off; off >>= 1) {
        if (t < off) sh[t] += sh[t + off];
        __syncthreads();
    }
    if (t == 0) g_blksum[b] = sh[0];
}
__global__ void k_scan2() {
    __shared__ int sh[256];
    int t = threadIdx.x;
    int v = (t < SCAN_NB) ? g_blksum[t] : 0;
    sh[t] = v;
    __syncthreads();
    for (int off = 1; off < 256; off <<= 1) {
        int add = (t >= off) ? sh[t - off] : 0;
        __syncthreads();
        sh[t] += add;
        __syncthreads();
    }
    if (t < SCAN_NB) g_blksum[t] = sh[t] - v;
    if (t == 255) g_rowptr[N_NODES] = sh[255];
}
__global__ void k_scan3() {   // local scan + self-loop fill + counts re-zero
    __shared__ int sh[256];
    int b = blockIdx.x, t = threadIdx.x;
    int idx = b * 256 + t;
    int v = (idx < N_NODES) ? g_counts[idx] + 1 : 0;
    sh[t] = v;
    __syncthreads();
    for (int off = 1; off < 256; off <<= 1) {
        int add = (t >= off) ? sh[t - off] : 0;
        __syncthreads();
        sh[t] += add;
        __syncthreads();
    }
    if (idx < N_NODES) {
        int p = g_blksum[b] + sh[t] - v;
        g_rowptr[idx] = p;
        g_srcidx[p] = idx;        // self loop first
        g_fill[idx] = p + 1;
        g_counts[idx] = 0;        // clean for next graph replay
    }
}

// ---------------- mma.sync bf16-split GEMM (double-buffered) -----------------
__device__ __forceinline__ void mma16816(float* c, const uint32_t* a, const uint32_t* b) {
    asm volatile(
        "mma.sync.aligned.m16n8k16.row.col.f32.bf16.bf16.f32 "
        "{%0,%1,%2,%3}, {%4,%5,%6,%7}, {%8,%9}, {%0,%1,%2,%3};"
        : "+f"(c[0]), "+f"(c[1]), "+f"(c[2]), "+f"(c[3])
        : "r"(a[0]), "r"(a[1]), "r"(a[2]), "r"(a[3]), "r"(b[0]), "r"(b[1]));
}
#define LDMX4(r, addr) \
    asm volatile("ldmatrix.sync.aligned.m8n8.x4.shared.b16 {%0,%1,%2,%3}, [%4];" \
        : "=r"((r)[0]), "=r"((r)[1]), "=r"((r)[2]), "=r"((r)[3]) : "r"(addr))
__device__ __forceinline__ uint32_t smem_u32(const void* p) {
    uint32_t a;
    asm("{ .reg .u64 t; cvta.to.shared.u64 t, %1; cvt.u32.u64 %0, t; }"
        : "=r"(a) : "l"(p));
    return a;
}

#define APAD   40            // bf16 row stride (80B), conflict-free ldmatrix
#define TILE_B 10240         // one 128x40 bf16 tile
#define BUF_B  (4 * TILE_B)  // Ah,Al,Bh,Bl per buffer
#define GEMM_DSMEM (2 * BUF_B)   // 81920

template <int AMODE>   // 0: A fp32 (convert on load), 1: A bf16 hi/lo pair
__global__ __launch_bounds__(256) void k_gemm_mma(
    const float* __restrict__ Af,
    const __nv_bfloat16* __restrict__ Abh, const __nv_bfloat16* __restrict__ Abl,
    const __nv_bfloat16* __restrict__ Bh,  const __nv_bfloat16* __restrict__ Bl,
    int M, int K,
    const float* __restrict__ a_s, const float* __restrict__ a_d,
    __nv_bfloat16* __restrict__ xwb,
    int gemm_blocks, const int* __restrict__ ei)
{
    // ---- extra blocks: grid-stride edge scatter (overlapped with GEMM) ----
    if ((int)blockIdx.x >= gemm_blocks) {
        int bid = blockIdx.x - gemm_blocks;
        int is64 = g_is64;
        for (int e = bid * 256 + (int)threadIdx.x; e < N_EDGES; e += SCAT_NB * 256) {
            int src, dst;
            if (is64) {
                src = (int)((const long long*)ei)[e];
                dst = (int)((const long long*)ei)[(size_t)N_EDGES + e];
            } else {
                src = ei[e];
                dst = ei[(size_t)N_EDGES + e];
            }
            g_srcidx[atomicAdd(&g_fill[dst], 1)] = src;
        }
        return;
    }

    extern __shared__ __align__(16) char dsm[];
    __shared__ float s_es[128], s_ed[128];

    int tid = threadIdx.x, lane = tid & 31, w = tid >> 5;
    int wm = w & 1, wn = w >> 1;
    int block_row = blockIdx.x * 128;
    int q = lane >> 2, qr = lane & 3;
    uint32_t base = smem_u32(dsm);

    float acc[4][4][4];
#pragma unroll
    for (int i = 0; i < 4; i++)
#pragma unroll
        for (int j = 0; j < 4; j++)
#pragma unroll
            for (int v = 0; v < 4; v++) acc[i][j][v] = 0.f;

    float4 pAf[4];
    uint2  pAh[4], pAl[4], pBh[4], pBl[4];
    const int nchunks = K >> 5;

#define LOAD_GLB(c) do {                                                        \
    int _k0 = (c) << 5;                                                         \
    _Pragma("unroll")                                                           \
    for (int it = 0; it < 4; it++) {                                            \
        int idx = tid + it * 256;                                               \
        int row = idx >> 3, col = (idx & 7) * 4;                                \
        int grow = block_row + row;                                             \
        if (grow >= M) grow = M - 1;                                            \
        if (AMODE == 0) {                                                       \
            pAf[it] = *(const float4*)(Af + (size_t)grow * K + _k0 + col);      \
        } else {                                                                \
            pAh[it] = *(const uint2*)(Abh + (size_t)grow * K + _k0 + col);      \
            pAl[it] = *(const uint2*)(Abl + (size_t)grow * K + _k0 + col);      \
        }                                                                       \
        pBh[it] = *(const uint2*)(Bh + (size_t)row * K + _k0 + col);            \
        pBl[it] = *(const uint2*)(Bl + (size_t)row * K + _k0 + col);            \
    } } while (0)

#define STORE_SMEM(buf) do {                                                    \
    char* _db = dsm + (buf) * BUF_B;                                            \
    _Pragma("unroll")                                                           \
    for (int it = 0; it < 4; it++) {                                            \
        int idx = tid + it * 256;                                               \
        int row = idx >> 3, col = (idx & 7) * 4;                                \
        uint32_t _o = (uint32_t)(row * APAD + col) * 2;                         \
        if (AMODE == 0) {                                                       \
            float4 v = pAf[it];                                                 \
            uint2 uh, ul;                                                       \
            uh.x = pack_bf2(v.x, v.y); uh.y = pack_bf2(v.z, v.w);               \
            ul.x = pack_bf2(v.x - __bfloat162float(__float2bfloat16(v.x)),      \
                            v.y - __bfloat162float(__float2bfloat16(v.y)));     \
            ul.y = pack_bf2(v.z - __bfloat162float(__float2bfloat16(v.z)),      \
                            v.w - __bfloat162float(__float2bfloat16(v.w)));     \
            *(uint2*)(_db + _o) = uh;                                           \
            *(uint2*)(_db + TILE_B + _o) = ul;                                  \
        } else {                                                                \
            *(uint2*)(_db + _o) = pAh[it];                                      \
            *(uint2*)(_db + TILE_B + _o) = pAl[it];                             \
        }                                                                       \
        *(uint2*)(_db + 2 * TILE_B + _o) = pBh[it];                             \
        *(uint2*)(_db + 3 * TILE_B + _o) = pBl[it];                             \
    } } while (0)

    LOAD_GLB(0);
    STORE_SMEM(0);
    __syncthreads();

    for (int c = 0; c < nchunks; c++) {
        int cb = c & 1;
        if (c + 1 < nchunks) LOAD_GLB(c + 1);
        uint32_t bAh = base + cb * BUF_B;
        uint32_t bAl = bAh + TILE_B, bBh = bAh + 2 * TILE_B, bBl = bAh + 3 * TILE_B;
#pragma unroll
        for (int ks = 0; ks < 32; ks += 16) {
            uint32_t ah[4][4], al[4][4];
#pragma unroll
            for (int i = 0; i < 4; i++) {
                int row = wm * 64 + i * 16 + (lane & 15);
                int col = ks + ((lane >> 4) << 3);
                uint32_t off = (uint32_t)(row * APAD + col) * 2;
                LDMX4(ah[i], bAh + off);
                LDMX4(al[i], bAl + off);
            }
#pragma unroll
            for (int jp = 0; jp < 2; jp++) {
                int nrow = wn * 32 + jp * 16 + ((lane >> 4) << 3) + (lane & 7);
                int col  = ks + (((lane >> 3) & 1) << 3);
                uint32_t off = (uint32_t)(nrow * APAD + col) * 2;
                uint32_t bh[4], bl[4];
                LDMX4(bh, bBh + off);
                LDMX4(bl, bBl + off);
#pragma unroll
                for (int i = 0; i < 4; i++) {
                    mma16816(acc[i][2 * jp],     ah[i], bh);
                    mma16816(acc[i][2 * jp],     ah[i], bl);
                    mma16816(acc[i][2 * jp],     al[i], bh);
                    mma16816(acc[i][2 * jp + 1], ah[i], bh + 2);
                    mma16816(acc[i][2 * jp + 1], ah[i], bl + 2);
                    mma16816(acc[i][2 * jp + 1], al[i], bh + 2);
                }
            }
        }
        if (c + 1 < nchunks) STORE_SMEM(!cb);
        __syncthreads();
    }

    // ---- epilogue: store xw (bf16) + fused es/ed (fp32) ----
    if (tid < 128) { s_es[tid] = 0.f; s_ed[tid] = 0.f; }
    __syncthreads();

    float2 asv[4], adv[4];
#pragma unroll
    for (int j = 0; j < 4; j++) {
        int col = wn * 32 + j * 8 + qr * 2;
        asv[j] = *(const float2*)(a_s + col);
        adv[j] = *(const float2*)(a_d + col);
    }
#pragma unroll
    for (int i = 0; i < 4; i++) {
        int lrow = wm * 64 + i * 16 + q;
        int grow0 = block_row + lrow;
        int grow1 = grow0 + 8;
        float e0s = 0.f, e0d = 0.f, e1s = 0.f, e1d = 0.f;
#pragma unroll
        for (int j = 0; j < 4; j++) {
            int col = wn * 32 + j * 8 + qr * 2;
            float d0 = acc[i][j][0], d1 = acc[i][j][1];
            float d2 = acc[i][j][2], d3 = acc[i][j][3];
            if (grow0 < M) *(uint32_t*)(xwb + (size_t)grow0 * HID2 + col) = pack_bf2(d0, d1);
            if (grow1 < M) *(uint32_t*)(xwb + (size_t)grow1 * HID2 + col) = pack_bf2(d2, d3);
            e0s += d0 * asv[j].x + d1 * asv[j].y;
            e0d += d0 * adv[j].x + d1 * adv[j].y;
            e1s += d2 * asv[j].x + d3 * asv[j].y;
            e1d += d2 * adv[j].x + d3 * adv[j].y;
        }
#pragma unroll
        for (int off = 1; off < 4; off <<= 1) {
            e0s += __shfl_xor_sync(0xffffffffu, e0s, off);
            e0d += __shfl_xor_sync(0xffffffffu, e0d, off);
            e1s += __shfl_xor_sync(0xffffffffu, e1s, off);
            e1d += __shfl_xor_sync(0xffffffffu, e1d, off);
        }
        if (qr == 0) {
            atomicAdd(&s_es[lrow], e0s);
            atomicAdd(&s_ed[lrow], e0d);
            atomicAdd(&s_es[lrow + 8], e1s);
            atomicAdd(&s_ed[lrow + 8], e1d);
        }
    }
    __syncthreads();
    if (tid < 128) {
        int grow = block_row + tid;
        if (grow < M) {
            g_es[grow] = s_es[tid];
            g_ed[grow] = s_ed[tid];
        }
    }
}

// ---------------- GAT aggregation: single pass, bf16 gather ------------------
template <int OUT>   // 0: fp32 out; 1: bf16 hi/lo pair out
__global__ void k_gat_agg(const __nv_bfloat16* __restrict__ xwb,
                          const float* __restrict__ bias,
                          float* __restrict__ out_f32,
                          __nv_bfloat16* __restrict__ oh,
                          __nv_bfloat16* __restrict__ ol)
{
    int node = (blockIdx.x * blockDim.x + threadIdx.x) >> 5;
    int lane = threadIdx.x & 31;
    if (node >= N_NODES) return;
    int beg = g_rowptr[node], end = g_rowptr[node + 1];
    float edv = g_ed[node];

    float ssum = 0.f;
    float4 acc = make_float4(0.f, 0.f, 0.f, 0.f);
    for (int base = beg; base < end; base += 32) {
        int i = base + lane;
        float alpha = 0.f;
        int sidx = 0;
        if (i < end) {
            sidx = g_srcidx[i];
            alpha = __expf(lrelu02(g_es[sidx] + edv));
        }
        ssum += alpha;
        int cnt = min(32, end - base);
        for (int j = 0; j < cnt; j++) {
            float a = __shfl_sync(0xffffffffu, alpha, j);
            int   s = __shfl_sync(0xffffffffu, sidx, j);
            uint2 u = ((const uint2*)(xwb + (size_t)s * HID2))[lane];
            float2 f0 = __bfloat1622float2(*(__nv_bfloat162*)&u.x);
            float2 f1 = __bfloat1622float2(*(__nv_bfloat162*)&u.y);
            acc.x += a * f0.x; acc.y += a * f0.y;
            acc.z += a * f1.x; acc.w += a * f1.y;
        }
    }
#pragma unroll
    for (int o = 16; o; o >>= 1) ssum += __shfl_xor_sync(0xffffffffu, ssum, o);
    float inv = 1.f / ssum;

    float4 b4 = ((const float4*)bias)[lane];
    float r0 = selu_f(acc.x * inv + b4.x), r1 = selu_f(acc.y * inv + b4.y);
    float r2 = selu_f(acc.z * inv + b4.z), r3 = selu_f(acc.w * inv + b4.w);
    if (OUT == 0) {
        ((float4*)(out_f32 + (size_t)node * HID2))[lane] = make_float4(r0, r1, r2, r3);
    } else {
        size_t off = (size_t)node * HID2 + lane * 4;
        uint2 uh, ul;
        uh.x = pack_bf2(r0, r1);
        uh.y = pack_bf2(r2, r3);
        ul.x = pack_bf2(r0 - __bfloat162float(__float2bfloat16(r0)),
                        r1 - __bfloat162float(__float2bfloat16(r1)));
        ul.y = pack_bf2(r2 - __bfloat162float(__float2bfloat16(r2)),
                        r3 - __bfloat162float(__float2bfloat16(r3)));
        *(uint2*)(oh + off) = uh;
        *(uint2*)(ol + off) = ul;
    }
}

// ---------------- pool + MLP + log_softmax -----------------------------------
__device__ __forceinline__ int lb_batch(const int* b, int n, int v) {
    int lo = 0, hi = n;
    while (lo < hi) {
        int mid = (lo + hi) >> 1;
        if (batch_at(b, mid) < v) lo = mid + 1; else hi = mid;
    }
    return lo;
}

__global__ void k_pool_mlp(const float* __restrict__ h,
                           const int* __restrict__ batch,
                           const float* __restrict__ fc1w, const float* __restrict__ fc1b,
                           const float* __restrict__ fc2w, const float* __restrict__ fc2b,
                           float* __restrict__ out)
{
    int g = blockIdx.x, t = threadIdx.x;
    __shared__ float pooled[HID2];
    __shared__ float hid[NHID];
    __shared__ float logits[2];

    int lo = lb_batch(batch, N_NODES, g);
    int hi = lb_batch(batch, N_NODES, g + 1);
    float s = 0.f;
    for (int i = lo; i < hi; i++) s += h[(size_t)i * HID2 + t];
    pooled[t] = selu_f(s / (float)max(hi - lo, 1));
    __syncthreads();

    if (t < NHID) {
        float a = fc1b[t];
#pragma unroll 8
        for (int c = 0; c < HID2; c++) a += pooled[c] * fc1w[c * NHID + t];
        hid[t] = selu_f(a);
    }
    __syncthreads();
    if (t < 2) {
        float a = fc2b[t];
#pragma unroll 8
        for (int j = 0; j < NHID; j++) a += hid[j] * fc2w[j * 2 + t];
        logits[t] = a;
    }
    __syncthreads();
    if (t == 0) {
        float l0 = logits[0], l1 = logits[1];
        float mx = fmaxf(l0, l1);
        float lse = mx + logf(expf(l0 - mx) + expf(l1 - mx));
        out[g * 2 + 0] = l0 - lse;
        out[g * 2 + 1] = l1 - lse;
    }
}

// ---------------- launcher ----------------------------------------------------
extern "C" void kernel_launch(void* const* d_in, const int* in_sizes, int n_in,
                              void* d_out, int out_size)
{
    const float* x     = (const float*)d_in[0];
    const int*   ei    = (const int*)d_in[1];
    const int*   batch = (const int*)d_in[2];
    const float* W1    = (const float*)d_in[3];
    const float* as1   = (const float*)d_in[4];
    const float* ad1   = (const float*)d_in[5];
    const float* b1    = (const float*)d_in[6];
    const float* W2    = (const float*)d_in[7];
    const float* as2   = (const float*)d_in[8];
    const float* ad2   = (const float*)d_in[9];
    const float* b2    = (const float*)d_in[10];
    const float* fc1w  = (const float*)d_in[11];
    const float* fc1b  = (const float*)d_in[12];
    const float* fc2w  = (const float*)d_in[13];
    const float* fc2b  = (const float*)d_in[14];
    float* out = (float*)d_out;

    __nv_bfloat16 *xwb, *h1h, *h1l, *w1h, *w1l, *w2h, *w2l;
    float* h;
    cudaGetSymbolAddress((void**)&xwb, g_xwb);
    cudaGetSymbolAddress((void**)&h,   g_h);
    cudaGetSymbolAddress((void**)&h1h, g_h1h);
    cudaGetSymbolAddress((void**)&h1l, g_h1l);
    cudaGetSymbolAddress((void**)&w1h, g_w1h);
    cudaGetSymbolAddress((void**)&w1l, g_w1l);
    cudaGetSymbolAddress((void**)&w2h, g_w2h);
    cudaGetSymbolAddress((void**)&w2l, g_w2l);

    cudaFuncSetAttribute(k_gemm_mma<0>, cudaFuncAttributeMaxDynamicSharedMemorySize, GEMM_DSMEM);
    cudaFuncSetAttribute(k_gemm_mma<1>, cudaFuncAttributeMaxDynamicSharedMemorySize, GEMM_DSMEM);

    const int GEMM_GRID = (N_NODES + 127) / 128;   // 391
    const int WARP_GRID = (N_NODES * 32 + 255) / 256;

    // --- histogram + weight split (merged) + scans ---
    k_histprep<<<HIST_NB + 384 + 64, 256>>>(ei, W1, W2);
    k_scan1<<<SCAN_NB, 256>>>();
    k_scan2<<<1, 256>>>();
    k_scan3<<<SCAN_NB, 256>>>();

    // --- layer 1 GEMM with edge-scatter overlapped as extra blocks ---
    k_gemm_mma<0><<<GEMM_GRID + SCAT_NB, 256, GEMM_DSMEM>>>(
        x, nullptr, nullptr, w1h, w1l, N_NODES, IN_F, as1, ad1, xwb, GEMM_GRID, ei);
    k_gat_agg<1><<<WARP_GRID, 256>>>(xwb, b1, nullptr, h1h, h1l);

    // --- layer 2 ---
    k_gemm_mma<1><<<GEMM_GRID, 256, GEMM_DSMEM>>>(
        nullptr, h1h, h1l, w2h, w2l, N_NODES, HID2, as2, ad2, xwb, GEMM_GRID, nullptr);
    k_gat_agg<0><<<WARP_GRID, 256>>>(xwb, b2, h, nullptr, nullptr);

    // --- pool + MLP + log_softmax ---
    k_pool_mlp<<<N_GRAPHS, HID2>>>(h, batch, fc1w, fc1b, fc2w, fc2b, out);
}

// round 8
// speedup vs baseline: 2.1204x; 1.0853x over previous
#include <cuda_runtime.h>
#include <cuda_bf16.h>
#include <cstdint>

#define N_NODES  50000
#define N_EDGES  800000
#define E_TOT    850000
#define IN_F     768
#define HID2     128
#define NHID     64
#define N_GRAPHS 128
#define CSR_NB   64                 // CSR worker blocks inside gemm1
#define NPB      782                // nodes per CSR block (64*782 >= 50000)

// ---------------- scratch (device globals; no runtime allocation) ----------
__device__ __nv_bfloat16 g_xwb[(size_t)N_NODES * HID2];
__device__ float g_h [(size_t)N_NODES * HID2];
__device__ __nv_bfloat16 g_h1h[(size_t)N_NODES * HID2];
__device__ __nv_bfloat16 g_h1l[(size_t)N_NODES * HID2];
__device__ __nv_bfloat16 g_w1h[(size_t)HID2 * IN_F];
__device__ __nv_bfloat16 g_w1l[(size_t)HID2 * IN_F];
__device__ __nv_bfloat16 g_w2h[(size_t)HID2 * HID2];
__device__ __nv_bfloat16 g_w2l[(size_t)HID2 * HID2];
__device__ float g_es[N_NODES];
__device__ float g_ed[N_NODES];
__device__ int   g_rowptr[N_NODES + 1];
__device__ int   g_counts[N_NODES];    // zero at load; re-zeroed each run in scan phase
__device__ int   g_fill[N_NODES];
__device__ int   g_srcidx[E_TOT];
__device__ int   g_blksum[CSR_NB];
__device__ volatile int g_bar[3];      // spin barriers; zeroed in k_prep each run
__device__ int   g_is64;

// ---------------- helpers ----------------------------------------------------
__device__ __forceinline__ float selu_f(float x) {
    const float sc = 1.0507009873554805f, al = 1.6732632423543772f;
    return x > 0.f ? sc * x : sc * al * expm1f(x);
}
__device__ __forceinline__ float lrelu02(float x) { return x > 0.f ? x : 0.2f * x; }
__device__ __forceinline__ uint32_t pack_bf2(float a, float b) {
    __nv_bfloat162 p(__float2bfloat16(a), __float2bfloat16(b));
    return *(uint32_t*)&p;
}
__device__ __forceinline__ int batch_at(const int* b, int i) {
    return g_is64 ? (int)((const long long*)b)[i] : b[i];
}

// ---------------- prep: weight transpose/split + dtype + barrier reset -------
// blocks [0,384): W1 conv; [384,448): W2 conv; 448: dtype detect + bar reset
__global__ void k_prep(const int* __restrict__ ei,
                       const float* __restrict__ W1, const float* __restrict__ W2) {
    int b = blockIdx.x, t = threadIdx.x;
    if (b < 384) {
        int idx = b * 256 + t;                   // IN_F*HID2 = 98304
        int n = idx & (HID2 - 1), k = idx >> 7;
        float v = W1[(size_t)k * HID2 + n];
        __nv_bfloat16 hb = __float2bfloat16(v);
        g_w1h[(size_t)n * IN_F + k] = hb;
        g_w1l[(size_t)n * IN_F + k] = __float2bfloat16(v - __bfloat162float(hb));
    } else if (b < 448) {
        int idx = (b - 384) * 256 + t;           // HID2*HID2 = 16384
        int n = idx & (HID2 - 1), k = idx >> 7;
        float v = W2[(size_t)k * HID2 + n];
        __nv_bfloat16 hb = __float2bfloat16(v);
        g_w2h[(size_t)n * HID2 + k] = hb;
        g_w2l[(size_t)n * HID2 + k] = __float2bfloat16(v - __bfloat162float(hb));
    } else {
        if (t < 32) {
            int nz = (ei[2 * t + 1] != 0) ? 1 : 0;
            uint32_t bal = __ballot_sync(0xffffffffu, nz);
            if (t == 0) g_is64 = (bal == 0u) ? 1 : 0;
        } else if (t >= 32 && t < 35) {
            g_bar[t - 32] = 0;
        }
    }
}

// ---------------- spin barrier across the CSR_NB co-resident blocks ----------
__device__ __forceinline__ void csr_bar(int i) {
    __syncthreads();
    if (threadIdx.x == 0) {
        __threadfence();
        atomicAdd((int*)&g_bar[i], 1);
        while (g_bar[i] < CSR_NB) { }
        __threadfence();
    }
    __syncthreads();
}

// ---------------- mma.sync bf16-split GEMM (double-buffered) -----------------
__device__ __forceinline__ void mma16816(float* c, const uint32_t* a, const uint32_t* b) {
    asm volatile(
        "mma.sync.aligned.m16n8k16.row.col.f32.bf16.bf16.f32 "
        "{%0,%1,%2,%3}, {%4,%5,%6,%7}, {%8,%9}, {%0,%1,%2,%3};"
        : "+f"(c[0]), "+f"(c[1]), "+f"(c[2]), "+f"(c[3])
        : "r"(a[0]), "r"(a[1]), "r"(a[2]), "r"(a[3]), "r"(b[0]), "r"(b[1]));
}
#define LDMX4(r, addr) \
    asm volatile("ldmatrix.sync.aligned.m8n8.x4.shared.b16 {%0,%1,%2,%3}, [%4];" \
        : "=r"((r)[0]), "=r"((r)[1]), "=r"((r)[2]), "=r"((r)[3]) : "r"(addr))
__device__ __forceinline__ uint32_t smem_u32(const void* p) {
    uint32_t a;
    asm("{ .reg .u64 t; cvta.to.shared.u64 t, %1; cvt.u32.u64 %0, t; }"
        : "=r"(a) : "l"(p));
    return a;
}

#define APAD   40            // bf16 row stride (80B), conflict-free ldmatrix
#define TILE_B 10240         // one 128x40 bf16 tile
// AMODE 0 (layer 1): tiles Ah,Bh,Bl (A-lo term dropped; W full hi/lo)
// AMODE 1 (layer 2): tiles Ah,Al,Bh,Bl (full 3-MMA split)
#define DSMEM0 (2 * 3 * TILE_B)   // 61440
#define DSMEM1 (2 * 4 * TILE_B)   // 81920

template <int AMODE>
__global__ __launch_bounds__(256) void k_gemm_mma(
    const float* __restrict__ Af,
    const __nv_bfloat16* __restrict__ Abh, const __nv_bfloat16* __restrict__ Abl,
    const __nv_bfloat16* __restrict__ Bh,  const __nv_bfloat16* __restrict__ Bl,
    int M, int K,
    const float* __restrict__ a_s, const float* __restrict__ a_d,
    __nv_bfloat16* __restrict__ xwb,
    int csr_blocks, const int* __restrict__ ei)
{
    // ============ CSR worker blocks (bids [0, csr_blocks)) ============
    if ((int)blockIdx.x < csr_blocks) {
        int b = blockIdx.x, t = threadIdx.x;
        int is64 = g_is64;
        // phase 1: degree histogram
        for (int e = b * 256 + t; e < N_EDGES; e += CSR_NB * 256) {
            int dst = is64 ? (int)((const long long*)ei)[(size_t)N_EDGES + e]
                           : ei[(size_t)N_EDGES + e];
            atomicAdd(&g_counts[dst], 1);
        }
        csr_bar(0);
        // phase 2: block-range scan (each block owns NPB nodes, 4 per thread)
        __shared__ int sh[256];
        __shared__ int s_pre;
        int start = b * NPB;
        int end = min(start + NPB, N_NODES);
        int i0 = start + t * 4;
        int c[4];
        int s = 0;
#pragma unroll
        for (int j = 0; j < 4; j++) {
            int i = i0 + j;
            c[j] = (i < end) ? g_counts[i] + 1 : 0;   // +1 self loop
            s += c[j];
        }
        sh[t] = s;
        __syncthreads();
        for (int off = 1; off < 256; off <<= 1) {
            int add = (t >= off) ? sh[t - off] : 0;
            __syncthreads();
            sh[t] += add;
            __syncthreads();
        }
        int excl = sh[t] - s;
        int total = sh[255];
        if (t == 0) g_blksum[b] = total;
        csr_bar(1);
        if (t == 0) {
            int p = 0;
            for (int bb = 0; bb < b; bb++) p += g_blksum[bb];
            s_pre = p;
        }
        __syncthreads();
        int off = s_pre + excl;
#pragma unroll
        for (int j = 0; j < 4; j++) {
            int i = i0 + j;
            if (i < end) {
                g_rowptr[i] = off;
                g_srcidx[off] = i;     // self loop first
                g_fill[i] = off + 1;
                g_counts[i] = 0;       // clean for next replay
                off += c[j];
            }
        }
        if (b == CSR_NB - 1 && t == 0) g_rowptr[N_NODES] = s_pre + total;
        csr_bar(2);
        // phase 3: edge scatter
        for (int e = b * 256 + t; e < N_EDGES; e += CSR_NB * 256) {
            int src, dst;
            if (is64) {
                src = (int)((const long long*)ei)[e];
                dst = (int)((const long long*)ei)[(size_t)N_EDGES + e];
            } else {
                src = ei[e];
                dst = ei[(size_t)N_EDGES + e];
            }
            g_srcidx[atomicAdd(&g_fill[dst], 1)] = src;
        }
        return;
    }

    // ============ GEMM blocks ============
    extern __shared__ __align__(16) char dsm[];
    __shared__ float s_es[128], s_ed[128];

    const int OFF_BH = (AMODE == 0) ? TILE_B : 2 * TILE_B;
    const int OFF_BL = OFF_BH + TILE_B;
    const int BUFB   = (AMODE == 0) ? 3 * TILE_B : 4 * TILE_B;

    int tid = threadIdx.x, lane = tid & 31, w = tid >> 5;
    int wm = w & 1, wn = w >> 1;
    int block_row = (blockIdx.x - csr_blocks) * 128;
    int q = lane >> 2, qr = lane & 3;
    uint32_t base = smem_u32(dsm);

    float acc[4][4][4];
#pragma unroll
    for (int i = 0; i < 4; i++)
#pragma unroll
        for (int j = 0; j < 4; j++)
#pragma unroll
            for (int v = 0; v < 4; v++) acc[i][j][v] = 0.f;

    float4 pAf[4];
    uint2  pAh[4], pAl[4], pBh[4], pBl[4];
    const int nchunks = K >> 5;

#define LOAD_GLB(c) do {                                                        \
    int _k0 = (c) << 5;                                                         \
    _Pragma("unroll")                                                           \
    for (int it = 0; it < 4; it++) {                                            \
        int idx = tid + it * 256;                                               \
        int row = idx >> 3, col = (idx & 7) * 4;                                \
        int grow = block_row + row;                                             \
        if (grow >= M) grow = M - 1;                                            \
        if (AMODE == 0) {                                                       \
            pAf[it] = *(const float4*)(Af + (size_t)grow * K + _k0 + col);      \
        } else {                                                                \
            pAh[it] = *(const uint2*)(Abh + (size_t)grow * K + _k0 + col);      \
            pAl[it] = *(const uint2*)(Abl + (size_t)grow * K + _k0 + col);      \
        }                                                                       \
        pBh[it] = *(const uint2*)(Bh + (size_t)row * K + _k0 + col);            \
        pBl[it] = *(const uint2*)(Bl + (size_t)row * K + _k0 + col);            \
    } } while (0)

#define STORE_SMEM(buf) do {                                                    \
    char* _db = dsm + (buf) * BUFB;                                             \
    _Pragma("unroll")                                                           \
    for (int it = 0; it < 4; it++) {                                            \
        int idx = tid + it * 256;                                               \
        int row = idx >> 3, col = (idx & 7) * 4;                                \
        uint32_t _o = (uint32_t)(row * APAD + col) * 2;                         \
        if (AMODE == 0) {                                                       \
            float4 v = pAf[it];                                                 \
            uint2 uh;                                                           \
            uh.x = pack_bf2(v.x, v.y); uh.y = pack_bf2(v.z, v.w);               \
            *(uint2*)(_db + _o) = uh;                                           \
        } else {                                                                \
            *(uint2*)(_db + _o) = pAh[it];                                      \
            *(uint2*)(_db + TILE_B + _o) = pAl[it];                             \
        }                                                                       \
        *(uint2*)(_db + OFF_BH + _o) = pBh[it];                                 \
        *(uint2*)(_db + OFF_BL + _o) = pBl[it];                                 \
    } } while (0)

    LOAD_GLB(0);
    STORE_SMEM(0);
    __syncthreads();

    for (int c = 0; c < nchunks; c++) {
        int cb = c & 1;
        if (c + 1 < nchunks) LOAD_GLB(c + 1);
        uint32_t bAh = base + cb * BUFB;
        uint32_t bAl = bAh + TILE_B;          // valid only AMODE 1
        uint32_t bBh = bAh + OFF_BH, bBl = bAh + OFF_BL;
#pragma unroll
        for (int ks = 0; ks < 32; ks += 16) {
            uint32_t ah[4][4], al[4][4];
#pragma unroll
            for (int i = 0; i < 4; i++) {
                int row = wm * 64 + i * 16 + (lane & 15);
                int col = ks + ((lane >> 4) << 3);
                uint32_t off = (uint32_t)(row * APAD + col) * 2;
                LDMX4(ah[i], bAh + off);
                if (AMODE == 1) LDMX4(al[i], bAl + off);
            }
#pragma unroll
            for (int jp = 0; jp < 2; jp++) {
                int nrow = wn * 32 + jp * 16 + ((lane >> 4) << 3) + (lane & 7);
                int col  = ks + (((lane >> 3) & 1) << 3);
                uint32_t off = (uint32_t)(nrow * APAD + col) * 2;
                uint32_t bh[4], bl[4];
                LDMX4(bh, bBh + off);
                LDMX4(bl, bBl + off);
#pragma unroll
                for (int i = 0; i < 4; i++) {
                    mma16816(acc[i][2 * jp],     ah[i], bh);
                    mma16816(acc[i][2 * jp],     ah[i], bl);
                    mma16816(acc[i][2 * jp + 1], ah[i], bh + 2);
                    mma16816(acc[i][2 * jp + 1], ah[i], bl + 2);
                    if (AMODE == 1) {
                        mma16816(acc[i][2 * jp],     al[i], bh);
                        mma16816(acc[i][2 * jp + 1], al[i], bh + 2);
                    }
                }
            }
        }
        if (c + 1 < nchunks) STORE_SMEM(!cb);
        __syncthreads();
    }

    // ---- epilogue: store xw (bf16) + fused es/ed (fp32) ----
    if (tid < 128) { s_es[tid] = 0.f; s_ed[tid] = 0.f; }
    __syncthreads();

    float2 asv[4], adv[4];
#pragma unroll
    for (int j = 0; j < 4; j++) {
        int col = wn * 32 + j * 8 + qr * 2;
        asv[j] = *(const float2*)(a_s + col);
        adv[j] = *(const float2*)(a_d + col);
    }
#pragma unroll
    for (int i = 0; i < 4; i++) {
        int lrow = wm * 64 + i * 16 + q;
        int grow0 = block_row + lrow;
        int grow1 = grow0 + 8;
        float e0s = 0.f, e0d = 0.f, e1s = 0.f, e1d = 0.f;
#pragma unroll
        for (int j = 0; j < 4; j++) {
            int col = wn * 32 + j * 8 + qr * 2;
            float d0 = acc[i][j][0], d1 = acc[i][j][1];
            float d2 = acc[i][j][2], d3 = acc[i][j][3];
            if (grow0 < M) *(uint32_t*)(xwb + (size_t)grow0 * HID2 + col) = pack_bf2(d0, d1);
            if (grow1 < M) *(uint32_t*)(xwb + (size_t)grow1 * HID2 + col) = pack_bf2(d2, d3);
            e0s += d0 * asv[j].x + d1 * asv[j].y;
            e0d += d0 * adv[j].x + d1 * adv[j].y;
            e1s += d2 * asv[j].x + d3 * asv[j].y;
            e1d += d2 * adv[j].x + d3 * adv[j].y;
        }
#pragma unroll
        for (int off = 1; off < 4; off <<= 1) {
            e0s += __shfl_xor_sync(0xffffffffu, e0s, off);
            e0d += __shfl_xor_sync(0xffffffffu, e0d, off);
            e1s += __shfl_xor_sync(0xffffffffu, e1s, off);
            e1d += __shfl_xor_sync(0xffffffffu, e1d, off);
        }
        if (qr == 0) {
            atomicAdd(&s_es[lrow], e0s);
            atomicAdd(&s_ed[lrow], e0d);
            atomicAdd(&s_es[lrow + 8], e1s);
            atomicAdd(&s_ed[lrow + 8], e1d);
        }
    }
    __syncthreads();
    if (tid < 128) {
        int grow = block_row + tid;
        if (grow < M) {
            g_es[grow] = s_es[tid];
            g_ed[grow] = s_ed[tid];
        }
    }
}

// ---------------- GAT aggregation: single pass, bf16 gather ------------------
template <int OUT>   // 0: fp32 out; 1: bf16 hi/lo pair out
__global__ void k_gat_agg(const __nv_bfloat16* __restrict__ xwb,
                          const float* __restrict__ bias,
                          float* __restrict__ out_f32,
                          __nv_bfloat16* __restrict__ oh,
                          __nv_bfloat16* __restrict__ ol)
{
    int node = (blockIdx.x * blockDim.x + threadIdx.x) >> 5;
    int lane = threadIdx.x & 31;
    if (node >= N_NODES) return;
    int beg = g_rowptr[node], end = g_rowptr[node + 1];
    float edv = g_ed[node];

    float ssum = 0.f;
    float4 acc = make_float4(0.f, 0.f, 0.f, 0.f);
    for (int base = beg; base < end; base += 32) {
        int i = base + lane;
        float alpha = 0.f;
        int sidx = 0;
        if (i < end) {
            sidx = g_srcidx[i];
            alpha = __expf(lrelu02(g_es[sidx] + edv));
        }
        ssum += alpha;
        int cnt = min(32, end - base);
        for (int j = 0; j < cnt; j++) {
            float a = __shfl_sync(0xffffffffu, alpha, j);
            int   s = __shfl_sync(0xffffffffu, sidx, j);
            uint2 u = ((const uint2*)(xwb + (size_t)s * HID2))[lane];
            float2 f0 = __bfloat1622float2(*(__nv_bfloat162*)&u.x);
            float2 f1 = __bfloat1622float2(*(__nv_bfloat162*)&u.y);
            acc.x += a * f0.x; acc.y += a * f0.y;
            acc.z += a * f1.x; acc.w += a * f1.y;
        }
    }
#pragma unroll
    for (int o = 16; o; o >>= 1) ssum += __shfl_xor_sync(0xffffffffu, ssum, o);
    float inv = 1.f / ssum;

    float4 b4 = ((const float4*)bias)[lane];
    float r0 = selu_f(acc.x * inv + b4.x), r1 = selu_f(acc.y * inv + b4.y);
    float r2 = selu_f(acc.z * inv + b4.z), r3 = selu_f(acc.w * inv + b4.w);
    if (OUT == 0) {
        ((float4*)(out_f32 + (size_t)node * HID2))[lane] = make_float4(r0, r1, r2, r3);
    } else {
        size_t off = (size_t)node * HID2 + lane * 4;
        uint2 uh, ul;
        uh.x = pack_bf2(r0, r1);
        uh.y = pack_bf2(r2, r3);
        ul.x = pack_bf2(r0 - __bfloat162float(__float2bfloat16(r0)),
                        r1 - __bfloat162float(__float2bfloat16(r1)));
        ul.y = pack_bf2(r2 - __bfloat162float(__float2bfloat16(r2)),
                        r3 - __bfloat162float(__float2bfloat16(r3)));
        *(uint2*)(oh + off) = uh;
        *(uint2*)(ol + off) = ul;
    }
}

// ---------------- pool + MLP + log_softmax -----------------------------------
__device__ __forceinline__ int lb_batch(const int* b, int n, int v) {
    int lo = 0, hi = n;
    while (lo < hi) {
        int mid = (lo + hi) >> 1;
        if (batch_at(b, mid) < v) lo = mid + 1; else hi = mid;
    }
    return lo;
}

__global__ void k_pool_mlp(const float* __restrict__ h,
                           const int* __restrict__ batch,
                           const float* __restrict__ fc1w, const float* __restrict__ fc1b,
                           const float* __restrict__ fc2w, const float* __restrict__ fc2b,
                           float* __restrict__ out)
{
    int g = blockIdx.x, t = threadIdx.x;
    __shared__ float pooled[HID2];
    __shared__ float hid[NHID];
    __shared__ float logits[2];

    int lo = lb_batch(batch, N_NODES, g);
    int hi = lb_batch(batch, N_NODES, g + 1);
    float s = 0.f;
    for (int i = lo; i < hi; i++) s += h[(size_t)i * HID2 + t];
    pooled[t] = selu_f(s / (float)max(hi - lo, 1));
    __syncthreads();

    if (t < NHID) {
        float a = fc1b[t];
#pragma unroll 8
        for (int c = 0; c < HID2; c++) a += pooled[c] * fc1w[c * NHID + t];
        hid[t] = selu_f(a);
    }
    __syncthreads();
    if (t < 2) {
        float a = fc2b[t];
#pragma unroll 8
        for (int j = 0; j < NHID; j++) a += hid[j] * fc2w[j * 2 + t];
        logits[t] = a;
    }
    __syncthreads();
    if (t == 0) {
        float l0 = logits[0], l1 = logits[1];
        float mx = fmaxf(l0, l1);
        float lse = mx + logf(expf(l0 - mx) + expf(l1 - mx));
        out[g * 2 + 0] = l0 - lse;
        out[g * 2 + 1] = l1 - lse;
    }
}

// ---------------- launcher ----------------------------------------------------
extern "C" void kernel_launch(void* const* d_in, const int* in_sizes, int n_in,
                              void* d_out, int out_size)
{
    const float* x     = (const float*)d_in[0];
    const int*   ei    = (const int*)d_in[1];
    const int*   batch = (const int*)d_in[2];
    const float* W1    = (const float*)d_in[3];
    const float* as1   = (const float*)d_in[4];
    const float* ad1   = (const float*)d_in[5];
    const float* b1    = (const float*)d_in[6];
    const float* W2    = (const float*)d_in[7];
    const float* as2   = (const float*)d_in[8];
    const float* ad2   = (const float*)d_in[9];
    const float* b2    = (const float*)d_in[10];
    const float* fc1w  = (const float*)d_in[11];
    const float* fc1b  = (const float*)d_in[12];
    const float* fc2w  = (const float*)d_in[13];
    const float* fc2b  = (const float*)d_in[14];
    float* out = (float*)d_out;

    __nv_bfloat16 *xwb, *h1h, *h1l, *w1h, *w1l, *w2h, *w2l;
    float* h;
    cudaGetSymbolAddress((void**)&xwb, g_xwb);
    cudaGetSymbolAddress((void**)&h,   g_h);
    cudaGetSymbolAddress((void**)&h1h, g_h1h);
    cudaGetSymbolAddress((void**)&h1l, g_h1l);
    cudaGetSymbolAddress((void**)&w1h, g_w1h);
    cudaGetSymbolAddress((void**)&w1l, g_w1l);
    cudaGetSymbolAddress((void**)&w2h, g_w2h);
    cudaGetSymbolAddress((void**)&w2l, g_w2l);

    cudaFuncSetAttribute(k_gemm_mma<0>, cudaFuncAttributeMaxDynamicSharedMemorySize, DSMEM0);
    cudaFuncSetAttribute(k_gemm_mma<1>, cudaFuncAttributeMaxDynamicSharedMemorySize, DSMEM1);

    const int GEMM_GRID = (N_NODES + 127) / 128;   // 391
    const int WARP_GRID = (N_NODES * 32 + 255) / 256;

    // --- weight split + dtype + barrier reset ---
    k_prep<<<449, 256>>>(ei, W1, W2);

    // --- layer 1: CSR build (64 worker blocks) + GEMM, one kernel ---
    k_gemm_mma<0><<<CSR_NB + GEMM_GRID, 256, DSMEM0>>>(
        x, nullptr, nullptr, w1h, w1l, N_NODES, IN_F, as1, ad1, xwb, CSR_NB, ei);
    k_gat_agg<1><<<WARP_GRID, 256>>>(xwb, b1, nullptr, h1h, h1l);

    // --- layer 2 ---
    k_gemm_mma<1><<<GEMM_GRID, 256, DSMEM1>>>(
        nullptr, h1h, h1l, w2h, w2l, N_NODES, HID2, as2, ad2, xwb, 0, nullptr);
    k_gat_agg<0><<<WARP_GRID, 256>>>(xwb, b2, h, nullptr, nullptr);

    // --- pool + MLP + log_softmax ---
    k_pool_mlp<<<N_GRAPHS, HID2>>>(h, batch, fc1w, fc1b, fc2w, fc2b, out);
}

// round 9
// speedup vs baseline: 2.2163x; 1.0452x over previous
#include <cuda_runtime.h>
#include <cuda_bf16.h>
#include <cstdint>

#define N_NODES  50000
#define N_EDGES  800000
#define E_TOT    850000
#define IN_F     768
#define HID2     128
#define NHID     64
#define N_GRAPHS 128
#define CSR_NB   64                 // CSR worker blocks inside gemm1
#define NPB      782                // nodes per CSR block (64*782 >= 50000)
#define MR       64                 // GEMM CTA tile rows

// ---------------- scratch (device globals; no runtime allocation) ----------
__device__ __nv_bfloat16 g_xwb[(size_t)N_NODES * HID2];
__device__ float g_h [(size_t)N_NODES * HID2];
__device__ __nv_bfloat16 g_h1h[(size_t)N_NODES * HID2];
__device__ __nv_bfloat16 g_w1h[(size_t)HID2 * IN_F];
__device__ __nv_bfloat16 g_w1l[(size_t)HID2 * IN_F];
__device__ __nv_bfloat16 g_w2h[(size_t)HID2 * HID2];
__device__ __nv_bfloat16 g_w2l[(size_t)HID2 * HID2];
__device__ float g_es[N_NODES];
__device__ float g_ed[N_NODES];
__device__ int   g_rowptr[N_NODES + 1];
__device__ int   g_counts[N_NODES];    // zero at load; re-zeroed each run
__device__ int   g_fill[N_NODES];
__device__ int   g_srcidx[E_TOT];
__device__ int   g_blksum[CSR_NB];
__device__ volatile int g_bar[3];
__device__ int   g_is64;

// ---------------- helpers ----------------------------------------------------
__device__ __forceinline__ float selu_f(float x) {
    const float sc = 1.0507009873554805f, al = 1.6732632423543772f;
    return x > 0.f ? sc * x : sc * al * expm1f(x);
}
__device__ __forceinline__ float lrelu02(float x) { return x > 0.f ? x : 0.2f * x; }
__device__ __forceinline__ uint32_t pack_bf2(float a, float b) {
    __nv_bfloat162 p(__float2bfloat16(a), __float2bfloat16(b));
    return *(uint32_t*)&p;
}
__device__ __forceinline__ int batch_at(const int* b, int i) {
    return g_is64 ? (int)((const long long*)b)[i] : b[i];
}

// ---------------- prep: weight transpose/split + dtype + barrier reset -------
__global__ void k_prep(const int* __restrict__ ei,
                       const float* __restrict__ W1, const float* __restrict__ W2) {
    int b = blockIdx.x, t = threadIdx.x;
    if (b < 384) {
        int idx = b * 256 + t;                   // IN_F*HID2 = 98304
        int n = idx & (HID2 - 1), k = idx >> 7;
        float v = W1[(size_t)k * HID2 + n];
        __nv_bfloat16 hb = __float2bfloat16(v);
        g_w1h[(size_t)n * IN_F + k] = hb;
        g_w1l[(size_t)n * IN_F + k] = __float2bfloat16(v - __bfloat162float(hb));
    } else if (b < 448) {
        int idx = (b - 384) * 256 + t;           // HID2*HID2 = 16384
        int n = idx & (HID2 - 1), k = idx >> 7;
        float v = W2[(size_t)k * HID2 + n];
        __nv_bfloat16 hb = __float2bfloat16(v);
        g_w2h[(size_t)n * HID2 + k] = hb;
        g_w2l[(size_t)n * HID2 + k] = __float2bfloat16(v - __bfloat162float(hb));
    } else {
        if (t < 32) {
            int nz = (ei[2 * t + 1] != 0) ? 1 : 0;
            uint32_t bal = __ballot_sync(0xffffffffu, nz);
            if (t == 0) g_is64 = (bal == 0u) ? 1 : 0;
        } else if (t >= 32 && t < 35) {
            g_bar[t - 32] = 0;
        }
    }
}

// ---------------- spin barrier across the CSR_NB co-resident blocks ----------
__device__ __forceinline__ void csr_bar(int i) {
    __syncthreads();
    if (threadIdx.x == 0) {
        __threadfence();
        atomicAdd((int*)&g_bar[i], 1);
        while (g_bar[i] < CSR_NB) { }
        __threadfence();
    }
    __syncthreads();
}

// ---------------- mma.sync bf16 GEMM, 64x128 tiles, 2 CTA/SM -----------------
__device__ __forceinline__ void mma16816(float* c, const uint32_t* a, const uint32_t* b) {
    asm volatile(
        "mma.sync.aligned.m16n8k16.row.col.f32.bf16.bf16.f32 "
        "{%0,%1,%2,%3}, {%4,%5,%6,%7}, {%8,%9}, {%0,%1,%2,%3};"
        : "+f"(c[0]), "+f"(c[1]), "+f"(c[2]), "+f"(c[3])
        : "r"(a[0]), "r"(a[1]), "r"(a[2]), "r"(a[3]), "r"(b[0]), "r"(b[1]));
}
#define LDMX4(r, addr) \
    asm volatile("ldmatrix.sync.aligned.m8n8.x4.shared.b16 {%0,%1,%2,%3}, [%4];" \
        : "=r"((r)[0]), "=r"((r)[1]), "=r"((r)[2]), "=r"((r)[3]) : "r"(addr))
__device__ __forceinline__ uint32_t smem_u32(const void* p) {
    uint32_t a;
    asm("{ .reg .u64 t; cvta.to.shared.u64 t, %1; cvt.u32.u64 %0, t; }"
        : "=r"(a) : "l"(p));
    return a;
}

#define APAD    40                   // bf16 row stride (80B), conflict-free ldmatrix
#define ATILE_B (MR * APAD * 2)      // 5120
#define BTILE_B (128 * APAD * 2)     // 10240
#define OFF_BH  ATILE_B
#define OFF_BL  (ATILE_B + BTILE_B)
#define BUF_B   (ATILE_B + 2 * BTILE_B)   // 25600
#define GEMM_DSMEM (2 * BUF_B)            // 51200

// A effectively bf16 (hi only); B = W^T in hi/lo split (full weight precision).
// AF=1: A fp32, convert on load. AF=0: A bf16.
template <int AF>
__global__ __launch_bounds__(256, 2) void k_gemm_mma(
    const float* __restrict__ Af, const __nv_bfloat16* __restrict__ Abh,
    const __nv_bfloat16* __restrict__ Bh, const __nv_bfloat16* __restrict__ Bl,
    int M, int K,
    const float* __restrict__ a_s, const float* __restrict__ a_d,
    __nv_bfloat16* __restrict__ xwb,
    int csr_blocks, const int* __restrict__ ei)
{
    // ============ CSR worker blocks (bids [0, csr_blocks)) ============
    if ((int)blockIdx.x < csr_blocks) {
        int b = blockIdx.x, t = threadIdx.x;
        int is64 = g_is64;
        for (int e = b * 256 + t; e < N_EDGES; e += CSR_NB * 256) {
            int dst = is64 ? (int)((const long long*)ei)[(size_t)N_EDGES + e]
                           : ei[(size_t)N_EDGES + e];
            atomicAdd(&g_counts[dst], 1);
        }
        csr_bar(0);
        __shared__ int sh[256];
        __shared__ int s_pre;
        int start = b * NPB;
        int end = min(start + NPB, N_NODES);
        int i0 = start + t * 4;
        int c[4];
        int s = 0;
#pragma unroll
        for (int j = 0; j < 4; j++) {
            int i = i0 + j;
            c[j] = (i < end) ? g_counts[i] + 1 : 0;
            s += c[j];
        }
        sh[t] = s;
        __syncthreads();
        for (int off = 1; off < 256; off <<= 1) {
            int add = (t >= off) ? sh[t - off] : 0;
            __syncthreads();
            sh[t] += add;
            __syncthreads();
        }
        int excl = sh[t] - s;
        int total = sh[255];
        if (t == 0) g_blksum[b] = total;
        csr_bar(1);
        if (t == 0) {
            int p = 0;
            for (int bb = 0; bb < b; bb++) p += g_blksum[bb];
            s_pre = p;
        }
        __syncthreads();
        int off = s_pre + excl;
#pragma unroll
        for (int j = 0; j < 4; j++) {
            int i = i0 + j;
            if (i < end) {
                g_rowptr[i] = off;
                g_srcidx[off] = i;
                g_fill[i] = off + 1;
                g_counts[i] = 0;
                off += c[j];
            }
        }
        if (b == CSR_NB - 1 && t == 0) g_rowptr[N_NODES] = s_pre + total;
        csr_bar(2);
        for (int e = b * 256 + t; e < N_EDGES; e += CSR_NB * 256) {
            int src, dst;
            if (is64) {
                src = (int)((const long long*)ei)[e];
                dst = (int)((const long long*)ei)[(size_t)N_EDGES + e];
            } else {
                src = ei[e];
                dst = ei[(size_t)N_EDGES + e];
            }
            g_srcidx[atomicAdd(&g_fill[dst], 1)] = src;
        }
        return;
    }

    // ============ GEMM blocks: 64 rows x 128 cols ============
    extern __shared__ __align__(16) char dsm[];
    __shared__ float s_es[MR], s_ed[MR];

    int tid = threadIdx.x, lane = tid & 31, w = tid >> 5;
    int wm = w & 1, wn = w >> 1;              // warp tile 32 x 32
    int block_row = (blockIdx.x - csr_blocks) * MR;
    int q = lane >> 2, qr = lane & 3;
    uint32_t base = smem_u32(dsm);

    float acc[2][4][4];
#pragma unroll
    for (int i = 0; i < 2; i++)
#pragma unroll
        for (int j = 0; j < 4; j++)
#pragma unroll
            for (int v = 0; v < 4; v++) acc[i][j][v] = 0.f;

    float4 pAf[2];
    uint2  pAh[2], pBh[4], pBl[4];
    const int nchunks = K >> 5;

#define LOAD_GLB(c) do {                                                        \
    int _k0 = (c) << 5;                                                         \
    _Pragma("unroll")                                                           \
    for (int it = 0; it < 2; it++) {                                            \
        int idx = tid + it * 256;                                               \
        int row = idx >> 3, col = (idx & 7) * 4;                                \
        int grow = block_row + row;                                             \
        if (grow >= M) grow = M - 1;                                            \
        if (AF) pAf[it] = *(const float4*)(Af + (size_t)grow * K + _k0 + col);  \
        else    pAh[it] = *(const uint2*)(Abh + (size_t)grow * K + _k0 + col);  \
    }                                                                           \
    _Pragma("unroll")                                                           \
    for (int it = 0; it < 4; it++) {                                            \
        int idx = tid + it * 256;                                               \
        int row = idx >> 3, col = (idx & 7) * 4;                                \
        pBh[it] = *(const uint2*)(Bh + (size_t)row * K + _k0 + col);            \
        pBl[it] = *(const uint2*)(Bl + (size_t)row * K + _k0 + col);            \
    } } while (0)

#define STORE_SMEM(buf) do {                                                    \
    char* _db = dsm + (buf) * BUF_B;                                            \
    _Pragma("unroll")                                                           \
    for (int it = 0; it < 2; it++) {                                            \
        int idx = tid + it * 256;                                               \
        int row = idx >> 3, col = (idx & 7) * 4;                                \
        uint32_t _o = (uint32_t)(row * APAD + col) * 2;                         \
        if (AF) {                                                               \
            float4 v = pAf[it];                                                 \
            uint2 uh;                                                           \
            uh.x = pack_bf2(v.x, v.y); uh.y = pack_bf2(v.z, v.w);               \
            *(uint2*)(_db + _o) = uh;                                           \
        } else {                                                                \
            *(uint2*)(_db + _o) = pAh[it];                                      \
        }                                                                       \
    }                                                                           \
    _Pragma("unroll")                                                           \
    for (int it = 0; it < 4; it++) {                                            \
        int idx = tid + it * 256;                                               \
        int row = idx >> 3, col = (idx & 7) * 4;                                \
        uint32_t _o = (uint32_t)(row * APAD + col) * 2;                         \
        *(uint2*)(_db + OFF_BH + _o) = pBh[it];                                 \
        *(uint2*)(_db + OFF_BL + _o) = pBl[it];                                 \
    } } while (0)

    LOAD_GLB(0);
    STORE_SMEM(0);
    __syncthreads();

    for (int c = 0; c < nchunks; c++) {
        int cb = c & 1;
        if (c + 1 < nchunks) LOAD_GLB(c + 1);
        uint32_t bA = base + cb * BUF_B;
        uint32_t bBh = bA + OFF_BH, bBl = bA + OFF_BL;
#pragma unroll
        for (int ks = 0; ks < 32; ks += 16) {
            uint32_t ah[2][4];
#pragma unroll
            for (int i = 0; i < 2; i++) {
                int row = wm * 32 + i * 16 + (lane & 15);
                int col = ks + ((lane >> 4) << 3);
                LDMX4(ah[i], bA + (uint32_t)(row * APAD + col) * 2);
            }
#pragma unroll
            for (int jp = 0; jp < 2; jp++) {
                int nrow = wn * 32 + jp * 16 + ((lane >> 4) << 3) + (lane & 7);
                int col  = ks + (((lane >> 3) & 1) << 3);
                uint32_t off = (uint32_t)(nrow * APAD + col) * 2;
                uint32_t bh[4], bl[4];
                LDMX4(bh, bBh + off);
                LDMX4(bl, bBl + off);
#pragma unroll
                for (int i = 0; i < 2; i++) {
                    mma16816(acc[i][2 * jp],     ah[i], bh);
                    mma16816(acc[i][2 * jp],     ah[i], bl);
                    mma16816(acc[i][2 * jp + 1], ah[i], bh + 2);
                    mma16816(acc[i][2 * jp + 1], ah[i], bl + 2);
                }
            }
        }
        if (c + 1 < nchunks) STORE_SMEM(!cb);
        __syncthreads();
    }

    // ---- epilogue: store xw (bf16) + fused es/ed (fp32) ----
    if (tid < MR) { s_es[tid] = 0.f; s_ed[tid] = 0.f; }
    __syncthreads();

    float2 asv[4], adv[4];
#pragma unroll
    for (int j = 0; j < 4; j++) {
        int col = wn * 32 + j * 8 + qr * 2;
        asv[j] = *(const float2*)(a_s + col);
        adv[j] = *(const float2*)(a_d + col);
    }
#pragma unroll
    for (int i = 0; i < 2; i++) {
        int lrow = wm * 32 + i * 16 + q;
        int grow0 = block_row + lrow;
        int grow1 = grow0 + 8;
        float e0s = 0.f, e0d = 0.f, e1s = 0.f, e1d = 0.f;
#pragma unroll
        for (int j = 0; j < 4; j++) {
            int col = wn * 32 + j * 8 + qr * 2;
            float d0 = acc[i][j][0], d1 = acc[i][j][1];
            float d2 = acc[i][j][2], d3 = acc[i][j][3];
            if (grow0 < M) *(uint32_t*)(xwb + (size_t)grow0 * HID2 + col) = pack_bf2(d0, d1);
            if (grow1 < M) *(uint32_t*)(xwb + (size_t)grow1 * HID2 + col) = pack_bf2(d2, d3);
            e0s += d0 * asv[j].x + d1 * asv[j].y;
            e0d += d0 * adv[j].x + d1 * adv[j].y;
            e1s += d2 * asv[j].x + d3 * asv[j].y;
            e1d += d2 * adv[j].x + d3 * adv[j].y;
        }
#pragma unroll
        for (int off = 1; off < 4; off <<= 1) {
            e0s += __shfl_xor_sync(0xffffffffu, e0s, off);
            e0d += __shfl_xor_sync(0xffffffffu, e0d, off);
            e1s += __shfl_xor_sync(0xffffffffu, e1s, off);
            e1d += __shfl_xor_sync(0xffffffffu, e1d, off);
        }
        if (qr == 0) {
            atomicAdd(&s_es[lrow], e0s);
            atomicAdd(&s_ed[lrow], e0d);
            atomicAdd(&s_es[lrow + 8], e1s);
            atomicAdd(&s_ed[lrow + 8], e1d);
        }
    }
    __syncthreads();
    if (tid < MR) {
        int grow = block_row + tid;
        if (grow < M) {
            g_es[grow] = s_es[tid];
            g_ed[grow] = s_ed[tid];
        }
    }
}

// ---------------- GAT aggregation: single pass, bf16 gather ------------------
template <int OUT>   // 0: fp32 out; 1: bf16 out (feeds next GEMM)
__global__ void k_gat_agg(const __nv_bfloat16* __restrict__ xwb,
                          const float* __restrict__ bias,
                          float* __restrict__ out_f32,
                          __nv_bfloat16* __restrict__ oh)
{
    int node = (blockIdx.x * blockDim.x + threadIdx.x) >> 5;
    int lane = threadIdx.x & 31;
    if (node >= N_NODES) return;
    int beg = g_rowptr[node], end = g_rowptr[node + 1];
    float edv = g_ed[node];

    float ssum = 0.f;
    float4 acc = make_float4(0.f, 0.f, 0.f, 0.f);
    for (int base = beg; base < end; base += 32) {
        int i = base + lane;
        float alpha = 0.f;
        int sidx = 0;
        if (i < end) {
            sidx = g_srcidx[i];
            alpha = __expf(lrelu02(g_es[sidx] + edv));
        }
        ssum += alpha;
        int cnt = min(32, end - base);
        for (int j = 0; j < cnt; j++) {
            float a = __shfl_sync(0xffffffffu, alpha, j);
            int   s = __shfl_sync(0xffffffffu, sidx, j);
            uint2 u = ((const uint2*)(xwb + (size_t)s * HID2))[lane];
            float2 f0 = __bfloat1622float2(*(__nv_bfloat162*)&u.x);
            float2 f1 = __bfloat1622float2(*(__nv_bfloat162*)&u.y);
            acc.x += a * f0.x; acc.y += a * f0.y;
            acc.z += a * f1.x; acc.w += a * f1.y;
        }
    }
#pragma unroll
    for (int o = 16; o; o >>= 1) ssum += __shfl_xor_sync(0xffffffffu, ssum, o);
    float inv = 1.f / ssum;

    float4 b4 = ((const float4*)bias)[lane];
    float r0 = selu_f(acc.x * inv + b4.x), r1 = selu_f(acc.y * inv + b4.y);
    float r2 = selu_f(acc.z * inv + b4.z), r3 = selu_f(acc.w * inv + b4.w);
    if (OUT == 0) {
        ((float4*)(out_f32 + (size_t)node * HID2))[lane] = make_float4(r0, r1, r2, r3);
    } else {
        uint2 uh;
        uh.x = pack_bf2(r0, r1);
        uh.y = pack_bf2(r2, r3);
        *(uint2*)(oh + (size_t)node * HID2 + lane * 4) = uh;
    }
}

// ---------------- pool + MLP + log_softmax -----------------------------------
__device__ __forceinline__ int lb_batch(const int* b, int n, int v) {
    int lo = 0, hi = n;
    while (lo < hi) {
        int mid = (lo + hi) >> 1;
        if (batch_at(b, mid) < v) lo = mid + 1; else hi = mid;
    }
    return lo;
}

__global__ void k_pool_mlp(const float* __restrict__ h,
                           const int* __restrict__ batch,
                           const float* __restrict__ fc1w, const float* __restrict__ fc1b,
                           const float* __restrict__ fc2w, const float* __restrict__ fc2b,
                           float* __restrict__ out)
{
    int g = blockIdx.x, t = threadIdx.x;
    __shared__ float pooled[HID2];
    __shared__ float hid[NHID];
    __shared__ float logits[2];

    int lo = lb_batch(batch, N_NODES, g);
    int hi = lb_batch(batch, N_NODES, g + 1);
    float s = 0.f;
    for (int i = lo; i < hi; i++) s += h[(size_t)i * HID2 + t];
    pooled[t] = selu_f(s / (float)max(hi - lo, 1));
    __syncthreads();

    if (t < NHID) {
        float a = fc1b[t];
#pragma unroll 8
        for (int c = 0; c < HID2; c++) a += pooled[c] * fc1w[c * NHID + t];
        hid[t] = selu_f(a);
    }
    __syncthreads();
    if (t < 2) {
        float a = fc2b[t];
#pragma unroll 8
        for (int j = 0; j < NHID; j++) a += hid[j] * fc2w[j * 2 + t];
        logits[t] = a;
    }
    __syncthreads();
    if (t == 0) {
        float l0 = logits[0], l1 = logits[1];
        float mx = fmaxf(l0, l1);
        float lse = mx + logf(expf(l0 - mx) + expf(l1 - mx));
        out[g * 2 + 0] = l0 - lse;
        out[g * 2 + 1] = l1 - lse;
    }
}

// ---------------- launcher ----------------------------------------------------
extern "C" void kernel_launch(void* const* d_in, const int* in_sizes, int n_in,
                              void* d_out, int out_size)
{
    const float* x     = (const float*)d_in[0];
    const int*   ei    = (const int*)d_in[1];
    const int*   batch = (const int*)d_in[2];
    const float* W1    = (const float*)d_in[3];
    const float* as1   = (const float*)d_in[4];
    const float* ad1   = (const float*)d_in[5];
    const float* b1    = (const float*)d_in[6];
    const float* W2    = (const float*)d_in[7];
    const float* as2   = (const float*)d_in[8];
    const float* ad2   = (const float*)d_in[9];
    const float* b2    = (const float*)d_in[10];
    const float* fc1w  = (const float*)d_in[11];
    const float* fc1b  = (const float*)d_in[12];
    const float* fc2w  = (const float*)d_in[13];
    const float* fc2b  = (const float*)d_in[14];
    float* out = (float*)d_out;

    __nv_bfloat16 *xwb, *h1h, *w1h, *w1l, *w2h, *w2l;
    float* h;
    cudaGetSymbolAddress((void**)&xwb, g_xwb);
    cudaGetSymbolAddress((void**)&h,   g_h);
    cudaGetSymbolAddress((void**)&h1h, g_h1h);
    cudaGetSymbolAddress((void**)&w1h, g_w1h);
    cudaGetSymbolAddress((void**)&w1l, g_w1l);
    cudaGetSymbolAddress((void**)&w2h, g_w2h);
    cudaGetSymbolAddress((void**)&w2l, g_w2l);

    cudaFuncSetAttribute(k_gemm_mma<0>, cudaFuncAttributeMaxDynamicSharedMemorySize, GEMM_DSMEM);
    cudaFuncSetAttribute(k_gemm_mma<1>, cudaFuncAttributeMaxDynamicSharedMemorySize, GEMM_DSMEM);

    const int GEMM_GRID = (N_NODES + MR - 1) / MR;   // 782
    const int WARP_GRID = (N_NODES * 32 + 255) / 256;

    // --- weight split + dtype + barrier reset ---
    k_prep<<<449, 256>>>(ei, W1, W2);

    // --- layer 1: CSR build (64 worker blocks) + GEMM, one kernel ---
    k_gemm_mma<1><<<CSR_NB + GEMM_GRID, 256, GEMM_DSMEM>>>(
        x, nullptr, w1h, w1l, N_NODES, IN_F, as1, ad1, xwb, CSR_NB, ei);
    k_gat_agg<1><<<WARP_GRID, 256>>>(xwb, b1, nullptr, h1h);

    // --- layer 2 ---
    k_gemm_mma<0><<<GEMM_GRID, 256, GEMM_DSMEM>>>(
        nullptr, h1h, w2h, w2l, N_NODES, HID2, as2, ad2, xwb, 0, nullptr);
    k_gat_agg<0><<<WARP_GRID, 256>>>(xwb, b2, h, nullptr);

    // --- pool + MLP + log_softmax ---
    k_pool_mlp<<<N_GRAPHS, HID2>>>(h, batch, fc1w, fc1b, fc2w, fc2b, out);
}

// round 10
// speedup vs baseline: 2.3445x; 1.0579x over previous
#include <cuda_runtime.h>
#include <cuda_bf16.h>
#include <cstdint>

#define N_NODES  50000
#define N_EDGES  800000
#define E_TOT    850000
#define IN_F     768
#define HID2     128
#define NHID     64
#define N_GRAPHS 128
#define CSR_NB   64
#define NPB      782
#define MR       64

// ---------------- scratch (device globals; no runtime allocation) ----------
__device__ __nv_bfloat16 g_xwb[(size_t)N_NODES * HID2];
__device__ float g_h [(size_t)N_NODES * HID2];
__device__ __nv_bfloat16 g_h1h[(size_t)N_NODES * HID2];
__device__ __nv_bfloat16 g_w1h[(size_t)HID2 * IN_F];
__device__ __nv_bfloat16 g_w1l[(size_t)HID2 * IN_F];
__device__ __nv_bfloat16 g_w2h[(size_t)HID2 * HID2];
__device__ __nv_bfloat16 g_w2l[(size_t)HID2 * HID2];
__device__ float g_es[N_NODES];
__device__ float g_ed[N_NODES];
__device__ int   g_rowptr[N_NODES + 1];
__device__ int   g_counts[N_NODES];
__device__ int   g_fill[N_NODES];
__device__ int   g_srcidx[E_TOT];
__device__ int   g_blksum[CSR_NB];
__device__ volatile int g_bar[3];
__device__ int   g_is64;

// ---------------- helpers ----------------------------------------------------
__device__ __forceinline__ float selu_f(float x) {
    const float sc = 1.0507009873554805f, al = 1.6732632423543772f;
    return x > 0.f ? sc * x : sc * al * expm1f(x);
}
__device__ __forceinline__ float lrelu02(float x) { return x > 0.f ? x : 0.2f * x; }
__device__ __forceinline__ uint32_t pack_bf2(float a, float b) {
    __nv_bfloat162 p(__float2bfloat16(a), __float2bfloat16(b));
    return *(uint32_t*)&p;
}
__device__ __forceinline__ int batch_at(const int* b, int i) {
    return g_is64 ? (int)((const long long*)b)[i] : b[i];
}

// ---------------- prep: weight transpose/split + dtype + barrier reset -------
__global__ void k_prep(const int* __restrict__ ei,
                       const float* __restrict__ W1, const float* __restrict__ W2) {
    int b = blockIdx.x, t = threadIdx.x;
    if (b < 384) {
        int idx = b * 256 + t;
        int n = idx & (HID2 - 1), k = idx >> 7;
        float v = W1[(size_t)k * HID2 + n];
        __nv_bfloat16 hb = __float2bfloat16(v);
        g_w1h[(size_t)n * IN_F + k] = hb;
        g_w1l[(size_t)n * IN_F + k] = __float2bfloat16(v - __bfloat162float(hb));
    } else if (b < 448) {
        int idx = (b - 384) * 256 + t;
        int n = idx & (HID2 - 1), k = idx >> 7;
        float v = W2[(size_t)k * HID2 + n];
        __nv_bfloat16 hb = __float2bfloat16(v);
        g_w2h[(size_t)n * HID2 + k] = hb;
        g_w2l[(size_t)n * HID2 + k] = __float2bfloat16(v - __bfloat162float(hb));
    } else {
        if (t < 32) {
            int nz = (ei[2 * t + 1] != 0) ? 1 : 0;
            uint32_t bal = __ballot_sync(0xffffffffu, nz);
            if (t == 0) g_is64 = (bal == 0u) ? 1 : 0;
        } else if (t >= 32 && t < 35) {
            g_bar[t - 32] = 0;
        }
    }
}

// ---------------- spin barrier across the CSR_NB co-resident blocks ----------
__device__ __forceinline__ void csr_bar(int i) {
    __syncthreads();
    if (threadIdx.x == 0) {
        __threadfence();
        atomicAdd((int*)&g_bar[i], 1);
        while (g_bar[i] < CSR_NB) { }
        __threadfence();
    }
    __syncthreads();
}

// ---------------- mma / ldmatrix / cp.async primitives -----------------------
__device__ __forceinline__ void mma16816(float* c, const uint32_t* a, const uint32_t* b) {
    asm volatile(
        "mma.sync.aligned.m16n8k16.row.col.f32.bf16.bf16.f32 "
        "{%0,%1,%2,%3}, {%4,%5,%6,%7}, {%8,%9}, {%0,%1,%2,%3};"
        : "+f"(c[0]), "+f"(c[1]), "+f"(c[2]), "+f"(c[3])
        : "r"(a[0]), "r"(a[1]), "r"(a[2]), "r"(a[3]), "r"(b[0]), "r"(b[1]));
}
#define LDMX4(r, addr) \
    asm volatile("ldmatrix.sync.aligned.m8n8.x4.shared.b16 {%0,%1,%2,%3}, [%4];" \
        : "=r"((r)[0]), "=r"((r)[1]), "=r"((r)[2]), "=r"((r)[3]) : "r"(addr))
#define CP16(dst, src) \
    asm volatile("cp.async.cg.shared.global [%0], [%1], 16;" \
        :: "r"(dst), "l"(src) : "memory")
#define CP_COMMIT() asm volatile("cp.async.commit_group;" ::: "memory")
#define CP_WAIT0()  asm volatile("cp.async.wait_group 0;" ::: "memory")

__device__ __forceinline__ uint32_t smem_u32(const void* p) {
    uint32_t a;
    asm("{ .reg .u64 t; cvta.to.shared.u64 t, %1; cvt.u32.u64 %0, t; }"
        : "=r"(a) : "l"(p));
    return a;
}

#define APAD    40                   // bf16 row stride (80B): 16B-aligned, ldmatrix conflict-free
#define ATILE_B (MR * APAD * 2)      // 5120
#define BTILE_B (128 * APAD * 2)     // 10240
#define OFF_BH  ATILE_B
#define OFF_BL  (ATILE_B + BTILE_B)
#define BUF_B   (ATILE_B + 2 * BTILE_B)   // 25600
#define GEMM_DSMEM (2 * BUF_B)            // 51200

// A bf16 (hi only); B = W^T hi/lo split. AF=1: A fp32 staged+converted; AF=0: A bf16 cp.async.
template <int AF>
__global__ __launch_bounds__(256, 3) void k_gemm_mma(
    const float* __restrict__ Af, const __nv_bfloat16* __restrict__ Abh,
    const __nv_bfloat16* __restrict__ Bh, const __nv_bfloat16* __restrict__ Bl,
    int M, int K,
    const float* __restrict__ a_s, const float* __restrict__ a_d,
    __nv_bfloat16* __restrict__ xwb,
    int csr_blocks, const int* __restrict__ ei)
{
    // ============ CSR worker blocks ============
    if ((int)blockIdx.x < csr_blocks) {
        int b = blockIdx.x, t = threadIdx.x;
        int is64 = g_is64;
        for (int e = b * 256 + t; e < N_EDGES; e += CSR_NB * 256) {
            int dst = is64 ? (int)((const long long*)ei)[(size_t)N_EDGES + e]
                           : ei[(size_t)N_EDGES + e];
            atomicAdd(&g_counts[dst], 1);
        }
        csr_bar(0);
        __shared__ int sh[256];
        __shared__ int s_pre;
        int start = b * NPB;
        int end = min(start + NPB, N_NODES);
        int i0 = start + t * 4;
        int c[4];
        int s = 0;
#pragma unroll
        for (int j = 0; j < 4; j++) {
            int i = i0 + j;
            c[j] = (i < end) ? g_counts[i] + 1 : 0;
            s += c[j];
        }
        sh[t] = s;
        __syncthreads();
        for (int off = 1; off < 256; off <<= 1) {
            int add = (t >= off) ? sh[t - off] : 0;
            __syncthreads();
            sh[t] += add;
            __syncthreads();
        }
        int excl = sh[t] - s;
        int total = sh[255];
        if (t == 0) g_blksum[b] = total;
        csr_bar(1);
        if (t == 0) {
            int p = 0;
            for (int bb = 0; bb < b; bb++) p += g_blksum[bb];
            s_pre = p;
        }
        __syncthreads();
        int off = s_pre + excl;
#pragma unroll
        for (int j = 0; j < 4; j++) {
            int i = i0 + j;
            if (i < end) {
                g_rowptr[i] = off;
                g_srcidx[off] = i;
                g_fill[i] = off + 1;
                g_counts[i] = 0;
                off += c[j];
            }
        }
        if (b == CSR_NB - 1 && t == 0) g_rowptr[N_NODES] = s_pre + total;
        csr_bar(2);
        for (int e = b * 256 + t; e < N_EDGES; e += CSR_NB * 256) {
            int src, dst;
            if (is64) {
                src = (int)((const long long*)ei)[e];
                dst = (int)((const long long*)ei)[(size_t)N_EDGES + e];
            } else {
                src = ei[e];
                dst = ei[(size_t)N_EDGES + e];
            }
            g_srcidx[atomicAdd(&g_fill[dst], 1)] = src;
        }
        return;
    }

    // ============ GEMM blocks: 64 rows x 128 cols ============
    extern __shared__ __align__(16) char dsm[];
    __shared__ float s_es[MR], s_ed[MR];

    int tid = threadIdx.x, lane = tid & 31, w = tid >> 5;
    int wm = w & 1, wn = w >> 1;
    int block_row = (blockIdx.x - csr_blocks) * MR;
    int q = lane >> 2, qr = lane & 3;
    uint32_t base = smem_u32(dsm);

    float acc[2][4][4];
#pragma unroll
    for (int i = 0; i < 2; i++)
#pragma unroll
        for (int j = 0; j < 4; j++)
#pragma unroll
            for (int v = 0; v < 4; v++) acc[i][j][v] = 0.f;

    float4 pAf[2];
    const int nchunks = K >> 5;

    // B (and AF=0 A) tiles via cp.async, 16B ops
#define ISSUE_CP(c, buf) do {                                                   \
    int _k0 = (c) << 5;                                                         \
    uint32_t _dbu = base + (buf) * BUF_B;                                       \
    _Pragma("unroll")                                                           \
    for (int it = 0; it < 2; it++) {                                            \
        int idx = tid + it * 256;                                               \
        int row = idx >> 2, cg = idx & 3;                                       \
        uint32_t _o = (uint32_t)(row * APAD + cg * 8) * 2;                      \
        CP16(_dbu + OFF_BH + _o, Bh + (size_t)row * K + _k0 + cg * 8);          \
        CP16(_dbu + OFF_BL + _o, Bl + (size_t)row * K + _k0 + cg * 8);          \
    }                                                                           \
    if (!AF) {                                                                  \
        int row = tid >> 2, cg = tid & 3;                                       \
        int grow = block_row + row;                                             \
        if (grow >= M) grow = M - 1;                                            \
        uint32_t _o = (uint32_t)(row * APAD + cg * 8) * 2;                      \
        CP16(_dbu + _o, Abh + (size_t)grow * K + _k0 + cg * 8);                 \
    }                                                                           \
    CP_COMMIT(); } while (0)

#define LDG_A(c) do {                                                           \
    int _k0 = (c) << 5;                                                         \
    _Pragma("unroll")                                                           \
    for (int it = 0; it < 2; it++) {                                            \
        int idx = tid + it * 256;                                               \
        int row = idx >> 3, col = (idx & 7) * 4;                                \
        int grow = block_row + row;                                             \
        if (grow >= M) grow = M - 1;                                            \
        pAf[it] = *(const float4*)(Af + (size_t)grow * K + _k0 + col);          \
    } } while (0)

#define STS_A(buf) do {                                                         \
    char* _db = dsm + (buf) * BUF_B;                                            \
    _Pragma("unroll")                                                           \
    for (int it = 0; it < 2; it++) {                                            \
        int idx = tid + it * 256;                                               \
        int row = idx >> 3, col = (idx & 7) * 4;                                \
        uint32_t _o = (uint32_t)(row * APAD + col) * 2;                         \
        float4 v = pAf[it];                                                     \
        uint2 uh;                                                               \
        uh.x = pack_bf2(v.x, v.y); uh.y = pack_bf2(v.z, v.w);                   \
        *(uint2*)(_db + _o) = uh;                                               \
    } } while (0)

    // prologue: chunk 0 into buffer 0
    ISSUE_CP(0, 0);
    if (AF) { LDG_A(0); STS_A(0); }
    CP_WAIT0();
    __syncthreads();

    for (int c = 0; c < nchunks; c++) {
        int cb = c & 1;
        if (c + 1 < nchunks) {
            ISSUE_CP(c + 1, !cb);
            if (AF) LDG_A(c + 1);
        }
        uint32_t bA = base + cb * BUF_B;
        uint32_t bBh = bA + OFF_BH, bBl = bA + OFF_BL;
#pragma unroll
        for (int ks = 0; ks < 32; ks += 16) {
            uint32_t ah[2][4];
#pragma unroll
            for (int i = 0; i < 2; i++) {
                int row = wm * 32 + i * 16 + (lane & 15);
                int col = ks + ((lane >> 4) << 3);
                LDMX4(ah[i], bA + (uint32_t)(row * APAD + col) * 2);
            }
#pragma unroll
            for (int jp = 0; jp < 2; jp++) {
                int nrow = wn * 32 + jp * 16 + ((lane >> 4) << 3) + (lane & 7);
                int col  = ks + (((lane >> 3) & 1) << 3);
                uint32_t off = (uint32_t)(nrow * APAD + col) * 2;
                uint32_t bh[4], bl[4];
                LDMX4(bh, bBh + off);
                LDMX4(bl, bBl + off);
#pragma unroll
                for (int i = 0; i < 2; i++) {
                    mma16816(acc[i][2 * jp],     ah[i], bh);
                    mma16816(acc[i][2 * jp],     ah[i], bl);
                    mma16816(acc[i][2 * jp + 1], ah[i], bh + 2);
                    mma16816(acc[i][2 * jp + 1], ah[i], bl + 2);
                }
            }
        }
        if (c + 1 < nchunks) {
            if (AF) STS_A(!cb);
            CP_WAIT0();
        }
        __syncthreads();
    }

    // ---- epilogue: store xw (bf16) + fused es/ed (fp32) ----
    if (tid < MR) { s_es[tid] = 0.f; s_ed[tid] = 0.f; }
    __syncthreads();

    float2 asv[4], adv[4];
#pragma unroll
    for (int j = 0; j < 4; j++) {
        int col = wn * 32 + j * 8 + qr * 2;
        asv[j] = *(const float2*)(a_s + col);
        adv[j] = *(const float2*)(a_d + col);
    }
#pragma unroll
    for (int i = 0; i < 2; i++) {
        int lrow = wm * 32 + i * 16 + q;
        int grow0 = block_row + lrow;
        int grow1 = grow0 + 8;
        float e0s = 0.f, e0d = 0.f, e1s = 0.f, e1d = 0.f;
#pragma unroll
        for (int j = 0; j < 4; j++) {
            int col = wn * 32 + j * 8 + qr * 2;
            float d0 = acc[i][j][0], d1 = acc[i][j][1];
            float d2 = acc[i][j][2], d3 = acc[i][j][3];
            if (grow0 < M) *(uint32_t*)(xwb + (size_t)grow0 * HID2 + col) = pack_bf2(d0, d1);
            if (grow1 < M) *(uint32_t*)(xwb + (size_t)grow1 * HID2 + col) = pack_bf2(d2, d3);
            e0s += d0 * asv[j].x + d1 * asv[j].y;
            e0d += d0 * adv[j].x + d1 * adv[j].y;
            e1s += d2 * asv[j].x + d3 * asv[j].y;
            e1d += d2 * adv[j].x + d3 * adv[j].y;
        }
#pragma unroll
        for (int off = 1; off < 4; off <<= 1) {
            e0s += __shfl_xor_sync(0xffffffffu, e0s, off);
            e0d += __shfl_xor_sync(0xffffffffu, e0d, off);
            e1s += __shfl_xor_sync(0xffffffffu, e1s, off);
            e1d += __shfl_xor_sync(0xffffffffu, e1d, off);
        }
        if (qr == 0) {
            atomicAdd(&s_es[lrow], e0s);
            atomicAdd(&s_ed[lrow], e0d);
            atomicAdd(&s_es[lrow + 8], e1s);
            atomicAdd(&s_ed[lrow + 8], e1d);
        }
    }
    __syncthreads();
    if (tid < MR) {
        int grow = block_row + tid;
        if (grow < M) {
            g_es[grow] = s_es[tid];
            g_ed[grow] = s_ed[tid];
        }
    }
}

// ---------------- GAT aggregation: single pass, bf16 gather ------------------
template <int OUT>
__global__ void k_gat_agg(const __nv_bfloat16* __restrict__ xwb,
                          const float* __restrict__ bias,
                          float* __restrict__ out_f32,
                          __nv_bfloat16* __restrict__ oh)
{
    int node = (blockIdx.x * blockDim.x + threadIdx.x) >> 5;
    int lane = threadIdx.x & 31;
    if (node >= N_NODES) return;
    int beg = g_rowptr[node], end = g_rowptr[node + 1];
    float edv = g_ed[node];

    float ssum = 0.f;
    float4 acc = make_float4(0.f, 0.f, 0.f, 0.f);
    for (int base = beg; base < end; base += 32) {
        int i = base + lane;
        float alpha = 0.f;
        int sidx = 0;
        if (i < end) {
            sidx = g_srcidx[i];
            alpha = __expf(lrelu02(g_es[sidx] + edv));
        }
        ssum += alpha;
        int cnt = min(32, end - base);
        for (int j = 0; j < cnt; j++) {
            float a = __shfl_sync(0xffffffffu, alpha, j);
            int   s = __shfl_sync(0xffffffffu, sidx, j);
            uint2 u = ((const uint2*)(xwb + (size_t)s * HID2))[lane];
            float2 f0 = __bfloat1622float2(*(__nv_bfloat162*)&u.x);
            float2 f1 = __bfloat1622float2(*(__nv_bfloat162*)&u.y);
            acc.x += a * f0.x; acc.y += a * f0.y;
            acc.z += a * f1.x; acc.w += a * f1.y;
        }
    }
#pragma unroll
    for (int o = 16; o; o >>= 1) ssum += __shfl_xor_sync(0xffffffffu, ssum, o);
    float inv = 1.f / ssum;

    float4 b4 = ((const float4*)bias)[lane];
    float r0 = selu_f(acc.x * inv + b4.x), r1 = selu_f(acc.y * inv + b4.y);
    float r2 = selu_f(acc.z * inv + b4.z), r3 = selu_f(acc.w * inv + b4.w);
    if (OUT == 0) {
        ((float4*)(out_f32 + (size_t)node * HID2))[lane] = make_float4(r0, r1, r2, r3);
    } else {
        uint2 uh;
        uh.x = pack_bf2(r0, r1);
        uh.y = pack_bf2(r2, r3);
        *(uint2*)(oh + (size_t)node * HID2 + lane * 4) = uh;
    }
}

// ---------------- pool + MLP + log_softmax -----------------------------------
__device__ __forceinline__ int lb_batch(const int* b, int n, int v) {
    int lo = 0, hi = n;
    while (lo < hi) {
        int mid = (lo + hi) >> 1;
        if (batch_at(b, mid) < v) lo = mid + 1; else hi = mid;
    }
    return lo;
}

__global__ void k_pool_mlp(const float* __restrict__ h,
                           const int* __restrict__ batch,
                           const float* __restrict__ fc1w, const float* __restrict__ fc1b,
                           const float* __restrict__ fc2w, const float* __restrict__ fc2b,
                           float* __restrict__ out)
{
    int g = blockIdx.x, t = threadIdx.x;
    __shared__ float pooled[HID2];
    __shared__ float hid[NHID];
    __shared__ float logits[2];

    int lo = lb_batch(batch, N_NODES, g);
    int hi = lb_batch(batch, N_NODES, g + 1);
    float s = 0.f;
    for (int i = lo; i < hi; i++) s += h[(size_t)i * HID2 + t];
    pooled[t] = selu_f(s / (float)max(hi - lo, 1));
    __syncthreads();

    if (t < NHID) {
        float a = fc1b[t];
#pragma unroll 8
        for (int c = 0; c < HID2; c++) a += pooled[c] * fc1w[c * NHID + t];
        hid[t] = selu_f(a);
    }
    __syncthreads();
    if (t < 2) {
        float a = fc2b[t];
#pragma unroll 8
        for (int j = 0; j < NHID; j++) a += hid[j] * fc2w[j * 2 + t];
        logits[t] = a;
    }
    __syncthreads();
    if (t == 0) {
        float l0 = logits[0], l1 = logits[1];
        float mx = fmaxf(l0, l1);
        float lse = mx + logf(expf(l0 - mx) + expf(l1 - mx));
        out[g * 2 + 0] = l0 - lse;
        out[g * 2 + 1] = l1 - lse;
    }
}

// ---------------- launcher ----------------------------------------------------
extern "C" void kernel_launch(void* const* d_in, const int* in_sizes, int n_in,
                              void* d_out, int out_size)
{
    const float* x     = (const float*)d_in[0];
    const int*   ei    = (const int*)d_in[1];
    const int*   batch = (const int*)d_in[2];
    const float* W1    = (const float*)d_in[3];
    const float* as1   = (const float*)d_in[4];
    const float* ad1   = (const float*)d_in[5];
    const float* b1    = (const float*)d_in[6];
    const float* W2    = (const float*)d_in[7];
    const float* as2   = (const float*)d_in[8];
    const float* ad2   = (const float*)d_in[9];
    const float* b2    = (const float*)d_in[10];
    const float* fc1w  = (const float*)d_in[11];
    const float* fc1b  = (const float*)d_in[12];
    const float* fc2w  = (const float*)d_in[13];
    const float* fc2b  = (const float*)d_in[14];
    float* out = (float*)d_out;

    __nv_bfloat16 *xwb, *h1h, *w1h, *w1l, *w2h, *w2l;
    float* h;
    cudaGetSymbolAddress((void**)&xwb, g_xwb);
    cudaGetSymbolAddress((void**)&h,   g_h);
    cudaGetSymbolAddress((void**)&h1h, g_h1h);
    cudaGetSymbolAddress((void**)&w1h, g_w1h);
    cudaGetSymbolAddress((void**)&w1l, g_w1l);
    cudaGetSymbolAddress((void**)&w2h, g_w2h);
    cudaGetSymbolAddress((void**)&w2l, g_w2l);

    cudaFuncSetAttribute(k_gemm_mma<0>, cudaFuncAttributeMaxDynamicSharedMemorySize, GEMM_DSMEM);
    cudaFuncSetAttribute(k_gemm_mma<1>, cudaFuncAttributeMaxDynamicSharedMemorySize, GEMM_DSMEM);

    const int GEMM_GRID = (N_NODES + MR - 1) / MR;   // 782
    const int WARP_GRID = (N_NODES * 32 + 255) / 256;

    // --- weight split + dtype + barrier reset ---
    k_prep<<<449, 256>>>(ei, W1, W2);

    // --- layer 1: CSR build (64 worker blocks) + GEMM, one kernel ---
    k_gemm_mma<1><<<CSR_NB + GEMM_GRID, 256, GEMM_DSMEM>>>(
        x, nullptr, w1h, w1l, N_NODES, IN_F, as1, ad1, xwb, CSR_NB, ei);
    k_gat_agg<1><<<WARP_GRID, 256>>>(xwb, b1, nullptr, h1h);

    // --- layer 2 ---
    k_gemm_mma<0><<<GEMM_GRID, 256, GEMM_DSMEM>>>(
        nullptr, h1h, w2h, w2l, N_NODES, HID2, as2, ad2, xwb, 0, nullptr);
    k_gat_agg<0><<<WARP_GRID, 256>>>(xwb, b2, h, nullptr);

    // --- pool + MLP + log_softmax ---
    k_pool_mlp<<<N_GRAPHS, HID2>>>(h, batch, fc1w, fc1b, fc2w, fc2b, out);
}